// round 3
// baseline (speedup 1.0000x reference)
#include <cuda_runtime.h>
#include <cuda_bf16.h>
#include <math.h>

#define NN 50000
#define NE 500000
#define D  64
#define EPS_BN 1e-5f
#define SNORM 0.0044721359549995794f   // 1/sqrt(50000)
#define DELTA_F 2.5f

// ---------------- scratch (device globals; no allocation allowed) ----------------
__device__ float g_PQ[(size_t)NN * 128];      // [P(64) | Q(64)] per node
__device__ float g_X [(size_t)NN * 448];      // [mean,mx,mn,std,var,sum (6x64) | h (64)]
__device__ float g_Z [(size_t)NN * 192];      // agg-side GEMM output
__device__ float g_hu[(size_t)NN * 64];
__device__ float g_ot[(size_t)NN * 64];
__device__ float g_hA[(size_t)NN * 64];
__device__ float g_hB[(size_t)NN * 64];
__device__ float g_scal[(size_t)NN * 2];      // amp, att per node
__device__ int   g_deg[NN];
__device__ int   g_rowptr[NN + 1];
__device__ int   g_cursor[NN];
__device__ int   g_srcsorted[NE];
__device__ float g_Bpq[64 * 128];             // packed [WM_top | WM_bot]
__device__ float g_Bz[448 * 192];             // packed update weights
__device__ float g_stats[256];                // sum1,sq1,sum2,sq2 (64 each)

// ---------------- CSR build ----------------
__global__ void zero_deg_kernel() {
    int i = blockIdx.x * blockDim.x + threadIdx.x;
    if (i < NN) g_deg[i] = 0;
}

__global__ void hist_kernel(const int* __restrict__ dst) {
    int e = blockIdx.x * blockDim.x + threadIdx.x;
    if (e < NE) atomicAdd(&g_deg[dst[e]], 1);
}

__global__ void scan_kernel() {
    __shared__ int sh[1024];
    int tid = threadIdx.x;
    int carry = 0;
    for (int base = 0; base < NN; base += 1024) {
        int i = base + tid;
        int v = (i < NN) ? g_deg[i] : 0;
        sh[tid] = v;
        __syncthreads();
        for (int off = 1; off < 1024; off <<= 1) {
            int t = (tid >= off) ? sh[tid - off] : 0;
            __syncthreads();
            sh[tid] += t;
            __syncthreads();
        }
        if (i < NN) {
            int incl = carry + sh[tid];
            g_rowptr[i + 1] = incl;
            g_cursor[i] = incl - v;
            if (i == 0) g_rowptr[0] = 0;
        }
        carry += sh[1023];
        __syncthreads();
    }
}

__global__ void scatter_kernel(const int* __restrict__ src, const int* __restrict__ dst) {
    int e = blockIdx.x * blockDim.x + threadIdx.x;
    if (e < NE) {
        int p = atomicAdd(&g_cursor[dst[e]], 1);
        g_srcsorted[p] = src[e];
    }
}

// ---------------- per-layer weight prepack ----------------
__global__ void zero_stats_kernel() { g_stats[threadIdx.x] = 0.f; }

__global__ void prepack_pq_kernel(const float* __restrict__ WM) {
    int idx = blockIdx.x * 256 + threadIdx.x;
    if (idx >= 64 * 128) return;
    int k = idx >> 7, j = idx & 127;
    g_Bpq[idx] = (j < 64) ? WM[k * 64 + j] : WM[(64 + k) * 64 + (j - 64)];
}

__global__ void prepack_z_kernel(const float* __restrict__ WU) {
    int idx = blockIdx.x * 256 + threadIdx.x;
    if (idx >= 448 * 192) return;
    int r = idx / 192, j = idx % 192;
    float v;
    if (r < 384) {
        int b = j >> 6, c = j & 63;
        int row = (b == 0) ? (64 + r) : ((b == 1) ? (448 + r) : (832 + r));
        v = WU[row * 64 + c];
    } else {
        int r2 = r - 384;
        v = (j < 64) ? WU[r2 * 64 + j] : 0.f;
    }
    g_Bz[idx] = v;
}

// ---------------- generic tiled fp32 GEMM: C[M,N] = A[M,K] @ B[K,N] ----------------
// BM=128, BN=64, BK=16, 256 threads, 8x4 micro-tile. K%16==0, N%64==0.
__global__ __launch_bounds__(256) void gemm_kernel(
    const float* __restrict__ A, const float* __restrict__ B,
    float* __restrict__ C, int M, int N, int K)
{
    __shared__ float As[16][128];
    __shared__ float Bs[16][64];
    int tid = threadIdx.x;
    int tx = tid & 15;       // col group (4 cols)
    int ty = tid >> 4;       // row group (8 rows)
    int rowBase = blockIdx.y * 128;
    int colBase = blockIdx.x * 64;
    int arow = tid & 127;
    int a2 = tid >> 7;       // 0..1
    int bk = tid >> 4;       // 0..15
    int bn = (tid & 15) * 4;

    float acc[8][4];
#pragma unroll
    for (int i = 0; i < 8; i++)
#pragma unroll
        for (int j = 0; j < 4; j++) acc[i][j] = 0.f;

    bool arowOK = (rowBase + arow) < M;
    const float* Aptr = A + (size_t)(rowBase + arow) * K;

    for (int k0 = 0; k0 < K; k0 += 16) {
#pragma unroll
        for (int j = 0; j < 2; j++) {
            int kk = a2 * 8 + j * 4;
            float4 av = make_float4(0.f, 0.f, 0.f, 0.f);
            if (arowOK) av = *(const float4*)(Aptr + k0 + kk);
            As[kk + 0][arow] = av.x;
            As[kk + 1][arow] = av.y;
            As[kk + 2][arow] = av.z;
            As[kk + 3][arow] = av.w;
        }
        float4 bv = *(const float4*)(B + (size_t)(k0 + bk) * N + colBase + bn);
        *(float4*)&Bs[bk][bn] = bv;
        __syncthreads();
#pragma unroll
        for (int k = 0; k < 16; k++) {
            float ar[8];
            *(float4*)&ar[0] = *(const float4*)&As[k][ty * 8];
            *(float4*)&ar[4] = *(const float4*)&As[k][ty * 8 + 4];
            float4 b = *(const float4*)&Bs[k][tx * 4];
#pragma unroll
            for (int i = 0; i < 8; i++) {
                acc[i][0] += ar[i] * b.x;
                acc[i][1] += ar[i] * b.y;
                acc[i][2] += ar[i] * b.z;
                acc[i][3] += ar[i] * b.w;
            }
        }
        __syncthreads();
    }
#pragma unroll
    for (int i = 0; i < 8; i++) {
        int gr = rowBase + ty * 8 + i;
        if (gr < M) {
            float4 v = make_float4(acc[i][0], acc[i][1], acc[i][2], acc[i][3]);
            *(float4*)(C + (size_t)gr * N + colBase + tx * 4) = v;
        }
    }
}

// ---------------- aggregation: one warp per node, msg recomputed on the fly ----------------
__global__ __launch_bounds__(256) void agg_kernel(
    const float* __restrict__ h_in, const float* __restrict__ bM)
{
    int v = blockIdx.x * 8 + (threadIdx.x >> 5);
    int lane = threadIdx.x & 31;
    if (v >= NN) return;
    int beg = g_rowptr[v], end = g_rowptr[v + 1];
    const float* qrow = g_PQ + (size_t)v * 128 + 64;
    float base0 = qrow[lane] + bM[lane];
    float base1 = qrow[32 + lane] + bM[32 + lane];
    float s0 = 0.f, s1 = 0.f, q0 = 0.f, q1 = 0.f;
    float mx0 = -INFINITY, mx1 = -INFINITY, mn0 = INFINITY, mn1 = INFINITY;
    for (int p = beg; p < end; p++) {
        int s = g_srcsorted[p];
        const float* pr = g_PQ + (size_t)s * 128;
        float m0 = pr[lane] + base0;
        float m1 = pr[32 + lane] + base1;
        s0 += m0; q0 += m0 * m0; mx0 = fmaxf(mx0, m0); mn0 = fminf(mn0, m0);
        s1 += m1; q1 += m1 * m1; mx1 = fmaxf(mx1, m1); mn1 = fminf(mn1, m1);
    }
    float deg = (float)(end - beg);
    float denom = fmaxf(deg, 1.f);
    float inv = 1.f / denom;
    float mean0 = s0 * inv, mean1 = s1 * inv;
    float var0 = fmaxf(q0 * inv - mean0 * mean0, 0.f);
    float var1 = fmaxf(q1 * inv - mean1 * mean1, 0.f);
    float std0 = sqrtf(var0 + 1e-30f);
    float std1 = sqrtf(var1 + 1e-30f);
    if (end == beg) { mx0 = mx1 = 0.f; mn0 = mn1 = 0.f; }
    float* xr = g_X + (size_t)v * 448;
    xr[lane] = mean0;        xr[32 + lane] = mean1;
    xr[64 + lane] = mx0;     xr[96 + lane] = mx1;
    xr[128 + lane] = mn0;    xr[160 + lane] = mn1;
    xr[192 + lane] = std0;   xr[224 + lane] = std1;
    xr[256 + lane] = var0;   xr[288 + lane] = var1;
    xr[320 + lane] = s0;     xr[352 + lane] = s1;
    xr[384 + lane] = h_in[(size_t)v * 64 + lane];
    xr[416 + lane] = h_in[(size_t)v * 64 + 32 + lane];
    if (lane == 0) {
        float logD = logf(deg + 1.f);
        g_scal[2 * v]     = logD * (1.f / DELTA_F);
        g_scal[2 * v + 1] = (logD > 0.f) ? (DELTA_F / logD) : 0.f;
    }
}

// ---------------- combine Z -> hu (+ BN1 stats) ----------------
__global__ __launch_bounds__(256) void combine_kernel(const float* __restrict__ bU) {
    int c  = threadIdx.x & 63;
    int rl = threadIdx.x >> 6;          // 0..3
    float bu = bU[c];
    float ls = 0.f, lq = 0.f;
    int base = blockIdx.x * 128;
    for (int i = 0; i < 32; i++) {
        int row = base + i * 4 + rl;
        if (row < NN) {
            float amp = g_scal[2 * row], att = g_scal[2 * row + 1];
            const float* zr = g_Z + (size_t)row * 192;
            float hu = (zr[c] + amp * zr[64 + c] + att * zr[128 + c] + bu) * SNORM;
            g_hu[(size_t)row * 64 + c] = hu;
            ls += hu; lq += hu * hu;
        }
    }
    __shared__ float red[256];
    red[threadIdx.x] = ls; __syncthreads();
    if (rl == 0) {
        float s = red[c] + red[64 + c] + red[128 + c] + red[192 + c];
        atomicAdd(&g_stats[c], s);
    }
    __syncthreads();
    red[threadIdx.x] = lq; __syncthreads();
    if (rl == 0) {
        float s = red[c] + red[64 + c] + red[128 + c] + red[192 + c];
        atomicAdd(&g_stats[64 + c], s);
    }
}

// ---------------- BN1 apply + mix GEMM + residual (+ BN2 stats) ----------------
__global__ __launch_bounds__(256) void mix_kernel(
    const float* __restrict__ h_in, const float* __restrict__ Wmix,
    const float* __restrict__ bmix, const float* __restrict__ gt,
    const float* __restrict__ bt)
{
    __shared__ float Wm[64 * 64];
    __shared__ float sc1[64], sh1[64];
    __shared__ float hb[8][64];
    __shared__ float ssum[8 * 64], ssq[8 * 64];
    int tid = threadIdx.x;
    for (int i = tid; i < 4096; i += 256) Wm[i] = Wmix[i];
    if (tid < 64) {
        float mu  = g_stats[tid] * (1.f / NN);
        float var = g_stats[64 + tid] * (1.f / NN) - mu * mu;
        float iv  = rsqrtf(fmaxf(var, 0.f) + EPS_BN);
        float s   = gt[tid] * iv;
        sc1[tid] = s;
        sh1[tid] = bt[tid] - mu * s;
    }
    __syncthreads();
    int w = tid >> 5, lane = tid & 31;
    float bm0 = bmix[lane], bm1 = bmix[lane + 32];
    float ls0 = 0.f, lq0 = 0.f, ls1 = 0.f, lq1 = 0.f;
    for (int row = blockIdx.x * 8 + w; row < NN; row += gridDim.x * 8) {
        float hu0 = g_hu[(size_t)row * 64 + lane];
        float hu1 = g_hu[(size_t)row * 64 + 32 + lane];
        hb[w][lane]      = hu0 * sc1[lane]      + sh1[lane];
        hb[w][lane + 32] = hu1 * sc1[lane + 32] + sh1[lane + 32];
        __syncwarp();
        float a0 = bm0, a1 = bm1;
#pragma unroll
        for (int k = 0; k < 64; k++) {
            float x = hb[w][k];
            a0 += x * Wm[k * 64 + lane];
            a1 += x * Wm[k * 64 + 32 + lane];
        }
        __syncwarp();
        float m0 = (a0 > 0.f) ? a0 : 0.01f * a0;
        float m1 = (a1 > 0.f) ? a1 : 0.01f * a1;
        float o0 = m0 + h_in[(size_t)row * 64 + lane];
        float o1 = m1 + h_in[(size_t)row * 64 + 32 + lane];
        g_ot[(size_t)row * 64 + lane]      = o0;
        g_ot[(size_t)row * 64 + 32 + lane] = o1;
        ls0 += o0; lq0 += o0 * o0;
        ls1 += o1; lq1 += o1 * o1;
    }
    ssum[w * 64 + lane] = ls0; ssum[w * 64 + 32 + lane] = ls1;
    ssq [w * 64 + lane] = lq0; ssq [w * 64 + 32 + lane] = lq1;
    __syncthreads();
    if (tid < 64) {
        float s = 0.f, q = 0.f;
#pragma unroll
        for (int i = 0; i < 8; i++) { s += ssum[i * 64 + tid]; q += ssq[i * 64 + tid]; }
        atomicAdd(&g_stats[128 + tid], s);
        atomicAdd(&g_stats[192 + tid], q);
    }
}

// ---------------- BN2 apply + relu + outer residual ----------------
__global__ void final_kernel(const float* __restrict__ h_in,
                             const float* __restrict__ go,
                             const float* __restrict__ bo,
                             float* __restrict__ h_out)
{
    int idx = blockIdx.x * blockDim.x + threadIdx.x;
    if (idx >= NN * 64) return;
    int c = idx & 63;
    float mu  = g_stats[128 + c] * (1.f / NN);
    float var = g_stats[192 + c] * (1.f / NN) - mu * mu;
    float iv  = rsqrtf(fmaxf(var, 0.f) + EPS_BN);
    float v = (g_ot[idx] - mu) * iv * go[c] + bo[c];
    h_out[idx] = fmaxf(v, 0.f) + h_in[idx];
}

// ---------------- host ----------------
extern "C" void kernel_launch(void* const* d_in, const int* in_sizes, int n_in,
                              void* d_out, int out_size)
{
    (void)in_sizes; (void)n_in; (void)out_size;
    const float* node_feat = (const float*)d_in[0];
    const int*   esrc = (const int*)d_in[2];
    const int*   edst = (const int*)d_in[3];
    const float* WM   = (const float*)d_in[4];
    const float* bM   = (const float*)d_in[5];
    const float* WU   = (const float*)d_in[6];
    const float* bU   = (const float*)d_in[7];
    const float* gt   = (const float*)d_in[8];
    const float* bt   = (const float*)d_in[9];
    const float* Wmix = (const float*)d_in[10];
    const float* bmix = (const float*)d_in[11];
    const float* go   = (const float*)d_in[12];
    const float* bo   = (const float*)d_in[13];
    float* out = (float*)d_out;

    float *pPQ, *pX, *pZ, *pBpq, *pBz, *phA, *phB;
    cudaGetSymbolAddress((void**)&pPQ,  g_PQ);
    cudaGetSymbolAddress((void**)&pX,   g_X);
    cudaGetSymbolAddress((void**)&pZ,   g_Z);
    cudaGetSymbolAddress((void**)&pBpq, g_Bpq);
    cudaGetSymbolAddress((void**)&pBz,  g_Bz);
    cudaGetSymbolAddress((void**)&phA,  g_hA);
    cudaGetSymbolAddress((void**)&phB,  g_hB);

    // CSR build (once per call, reused by all 4 layers)
    zero_deg_kernel<<<(NN + 255) / 256, 256>>>();
    hist_kernel<<<(NE + 255) / 256, 256>>>(edst);
    scan_kernel<<<1, 1024>>>();
    scatter_kernel<<<(NE + 255) / 256, 256>>>(esrc, edst);

    const float* h_in = node_feat;
    float* hs[2] = { phA, phB };
    for (int l = 0; l < 4; l++) {
        zero_stats_kernel<<<1, 256>>>();
        prepack_pq_kernel<<<(64 * 128 + 255) / 256, 256>>>(WM + (size_t)l * 128 * 64);
        prepack_z_kernel<<<(448 * 192 + 255) / 256, 256>>>(WU + (size_t)l * 1216 * 64);
        // PQ = h @ [WM_top | WM_bot] : [N,64]@[64,128]
        gemm_kernel<<<dim3(2, 391), 256>>>(h_in, pBpq, pPQ, NN, 128, 64);
        // aggregation (msg = P[src] + Q[dst] + bM, never materialized)
        agg_kernel<<<(NN + 7) / 8, 256>>>(h_in, bM + l * 64);
        // Z = [agg | h] @ Bz : [N,448]@[448,192]
        gemm_kernel<<<dim3(3, 391), 256>>>(pX, pBz, pZ, NN, 192, 448);
        combine_kernel<<<(NN + 127) / 128, 256>>>(bU + l * 64);
        mix_kernel<<<782, 256>>>(h_in, Wmix + (size_t)l * 64 * 64, bmix + l * 64,
                                 gt + l * 64, bt + l * 64);
        float* h_out = (l == 3) ? out : hs[l & 1];
        final_kernel<<<(NN * 64 + 255) / 256, 256>>>(h_in, go + l * 64, bo + l * 64, h_out);
        h_in = h_out;
    }
}

// round 6
// speedup vs baseline: 1.2571x; 1.2571x over previous
#include <cuda_runtime.h>
#include <cuda_bf16.h>
#include <math.h>
#include <stdint.h>

#define NN 50000
#define NPAD 50048              // 391 * 128
#define NE 500000
#define EPS_BN 1e-5f
#define SNORM 0.0044721359549995794f   // 1/sqrt(50000)
#define DELTA_F 2.5f
#define NTILES 391

// ======================= helpers =======================
__device__ __forceinline__ uint32_t smem_u32(const void* p) {
    uint32_t a;
    asm("{ .reg .u64 t; cvta.to.shared.u64 t, %1; cvt.u32.u64 %0, t; }" : "=r"(a) : "l"(p));
    return a;
}
__device__ __forceinline__ void ldsm4(uint32_t a[4], uint32_t addr) {
    asm volatile("ldmatrix.sync.aligned.m8n8.x4.shared.b16 {%0,%1,%2,%3}, [%4];"
                 : "=r"(a[0]), "=r"(a[1]), "=r"(a[2]), "=r"(a[3]) : "r"(addr));
}
__device__ __forceinline__ void ldsm4t(uint32_t a[4], uint32_t addr) {
    asm volatile("ldmatrix.sync.aligned.m8n8.x4.trans.shared.b16 {%0,%1,%2,%3}, [%4];"
                 : "=r"(a[0]), "=r"(a[1]), "=r"(a[2]), "=r"(a[3]) : "r"(addr));
}
__device__ __forceinline__ void mma16816(float* c, const uint32_t a[4],
                                         uint32_t b0, uint32_t b1) {
    asm volatile("mma.sync.aligned.m16n8k16.row.col.f32.bf16.bf16.f32 "
        "{%0,%1,%2,%3}, {%4,%5,%6,%7}, {%8,%9}, {%0,%1,%2,%3};"
        : "+f"(c[0]), "+f"(c[1]), "+f"(c[2]), "+f"(c[3])
        : "r"(a[0]), "r"(a[1]), "r"(a[2]), "r"(a[3]), "r"(b0), "r"(b1));
}

// ======================= scratch (device globals) =======================
__device__ float g_PQ[(size_t)NPAD * 128];     // [P(64) | Q(64)] per node
__device__ float g_X [(size_t)NPAD * 448];     // [mean,mx,mn,std,var,sum | h]; padded rows stay 0
__device__ float g_hu[(size_t)NN * 64];
__device__ float g_ot[(size_t)NN * 64];
__device__ float g_hA[(size_t)NN * 64];
__device__ float g_hB[(size_t)NN * 64];
__device__ float g_scal[(size_t)NPAD * 2];     // amp, att (padded rows stay 0)
__device__ int   g_deg[NN];
__device__ int   g_rowptr[NN + 1];
__device__ int   g_cursor[NN];
__device__ int   g_srcsorted[NE];
__device__ uint32_t g_BzKh[448 * 96];          // Bz [448][192] bf16 hi, K-major, n-pairs
__device__ uint32_t g_BzKl[448 * 96];
__device__ uint32_t g_BpqKh[64 * 64];          // Bpq [64][128] bf16 hi, K-major, n-pairs
__device__ uint32_t g_BpqKl[64 * 64];
__device__ float g_stats[256];                 // BN1 sum/sq, BN2 sum/sq

// ======================= CSR build =======================
__global__ void zero_deg_kernel() {
    int i = blockIdx.x * blockDim.x + threadIdx.x;
    if (i < NN) g_deg[i] = 0;
}
__global__ void hist_kernel(const int* __restrict__ dst) {
    int e = blockIdx.x * blockDim.x + threadIdx.x;
    if (e < NE) atomicAdd(&g_deg[dst[e]], 1);
}
__global__ void scan_kernel() {
    __shared__ int sh[1024];
    int tid = threadIdx.x;
    int carry = 0;
    for (int base = 0; base < NN; base += 1024) {
        int i = base + tid;
        int v = (i < NN) ? g_deg[i] : 0;
        sh[tid] = v;
        __syncthreads();
        for (int off = 1; off < 1024; off <<= 1) {
            int t = (tid >= off) ? sh[tid - off] : 0;
            __syncthreads();
            sh[tid] += t;
            __syncthreads();
        }
        if (i < NN) {
            int incl = carry + sh[tid];
            g_rowptr[i + 1] = incl;
            g_cursor[i] = incl - v;
            if (i == 0) g_rowptr[0] = 0;
        }
        carry += sh[1023];
        __syncthreads();
    }
}
__global__ void scatter_kernel(const int* __restrict__ src, const int* __restrict__ dst) {
    int e = blockIdx.x * blockDim.x + threadIdx.x;
    if (e < NE) {
        int p = atomicAdd(&g_cursor[dst[e]], 1);
        g_srcsorted[p] = src[e];
    }
}

// ======================= weight prepack =======================
__global__ void zero_stats_kernel() { g_stats[threadIdx.x] = 0.f; }

__device__ __forceinline__ void split_pack(float v0, float v1, uint32_t& uh, uint32_t& ul) {
    __nv_bfloat162 hp, lp;
    hp.x = __float2bfloat16(v0); hp.y = __float2bfloat16(v1);
    lp.x = __float2bfloat16(v0 - __bfloat162float(hp.x));
    lp.y = __float2bfloat16(v1 - __bfloat162float(hp.y));
    uh = *(uint32_t*)&hp; ul = *(uint32_t*)&lp;
}

__global__ void prepack_pq_kernel(const float* __restrict__ WM) {
    int idx = blockIdx.x * 256 + threadIdx.x;
    if (idx >= 64 * 64) return;
    int k = idx >> 6, n2 = idx & 63;
    float v[2];
#pragma unroll
    for (int j = 0; j < 2; j++) {
        int n = n2 * 2 + j;
        v[j] = (n < 64) ? WM[k * 64 + n] : WM[(64 + k) * 64 + (n - 64)];
    }
    uint32_t uh, ul; split_pack(v[0], v[1], uh, ul);
    g_BpqKh[idx] = uh; g_BpqKl[idx] = ul;
}

__global__ void prepack_z_kernel(const float* __restrict__ WU) {
    int idx = blockIdx.x * 256 + threadIdx.x;
    if (idx >= 448 * 96) return;
    int k = idx / 96, n2 = idx - k * 96;
    float v[2];
#pragma unroll
    for (int j = 0; j < 2; j++) {
        int n = n2 * 2 + j;
        float val;
        if (k < 384) {
            int b = n >> 6;
            int wrow = ((b == 0) ? 64 : (b == 1) ? 448 : 832) + k;
            val = WU[wrow * 64 + (n & 63)];
        } else {
            val = (n < 64) ? WU[(k - 384) * 64 + n] : 0.f;
        }
        v[j] = val;
    }
    uint32_t uh, ul; split_pack(v[0], v[1], uh, ul);
    g_BzKh[idx] = uh; g_BzKl[idx] = ul;
}

// ======================= PQ MMA: PQ[NPAD,128] = h[*,64] @ Bpq[64,128] =======================
// smem: A hi/lo 128 x 144B, B hi/lo 64 x 272B. stage reuses [0, 67584).
#define PS_AH 0
#define PS_AL 18432
#define PS_BH 36864
#define PS_BL 54272
#define P_SMEM 71680

__global__ __launch_bounds__(256) void pqmma_kernel(const float* __restrict__ h_in)
{
    extern __shared__ char dsm[];
    uint32_t sb = smem_u32(dsm);
    int tid = threadIdx.x, w = tid >> 5, l = tid & 31, g = l >> 2, t = l & 3;
    int tB = blockIdx.x * 128;

    float c[64];
#pragma unroll
    for (int i = 0; i < 64; i++) c[i] = 0.f;

    // A: h rows [tB, tB+128) -> bf16 hi/lo
    for (int i = tid; i < 4096; i += 256) {
        int row = i >> 5, c2 = i & 31;
        int gr = tB + row;
        float2 v = make_float2(0.f, 0.f);
        if (gr < NN) v = *(const float2*)(h_in + (size_t)gr * 64 + c2 * 2);
        uint32_t u0 = __float_as_uint(v.x), u1 = __float_as_uint(v.y);
        uint32_t hi2 = __byte_perm(u0, u1, 0x7632);
        float lo0 = v.x - __uint_as_float(u0 & 0xFFFF0000u);
        float lo1 = v.y - __uint_as_float(u1 & 0xFFFF0000u);
        __nv_bfloat162 lp = __floats2bfloat162_rn(lo0, lo1);
        *(uint32_t*)(dsm + PS_AH + row * 144 + c2 * 4) = hi2;
        *(uint32_t*)(dsm + PS_AL + row * 144 + c2 * 4) = *(uint32_t*)&lp;
    }
    // B: [64][64] uint32 pairs
    for (int i = tid; i < 4096; i += 256) {
        int kr = i >> 6, n2 = i & 63;
        uint32_t off = kr * 272 + n2 * 4;
        *(uint32_t*)(dsm + PS_BH + off) = g_BpqKh[i];
        *(uint32_t*)(dsm + PS_BL + off) = g_BpqKl[i];
    }
    __syncthreads();

    uint32_t aAoff = (uint32_t)(w * 16 + (l & 15)) * 144 + (uint32_t)(l >> 4) * 16;
    uint32_t aBoff = (uint32_t)(l & 15) * 272 + (uint32_t)(l >> 4) * 16;
#pragma unroll
    for (int p = 0; p < 3; p++) {
        uint32_t aA = sb + (p == 2 ? PS_AL : PS_AH) + aAoff;
        uint32_t aB = sb + (p == 1 ? PS_BL : PS_BH) + aBoff;
#pragma unroll
        for (int ks = 0; ks < 4; ks++) {
            uint32_t a[4];
            ldsm4(a, aA + ks * 32);
#pragma unroll
            for (int nn = 0; nn < 8; nn++) {
                uint32_t b[4];
                ldsm4t(b, aB + ks * 16 * 272 + nn * 32);
                mma16816(c + nn * 8,     a, b[0], b[1]);
                mma16816(c + nn * 8 + 4, a, b[2], b[3]);
            }
        }
    }
    __syncthreads();

    // stage [128][132] then coalesced store
    float* stage = (float*)dsm;
    int r0 = w * 16 + g, r1 = r0 + 8;
#pragma unroll
    for (int jj = 0; jj < 16; jj++) {
        int col = jj * 8 + 2 * t;
        stage[r0 * 132 + col]     = c[jj * 4 + 0];
        stage[r0 * 132 + col + 1] = c[jj * 4 + 1];
        stage[r1 * 132 + col]     = c[jj * 4 + 2];
        stage[r1 * 132 + col + 1] = c[jj * 4 + 3];
    }
    __syncthreads();
    for (int i = tid; i < 4096; i += 256) {
        int row = i >> 5, c4 = (i & 31) * 4;
        float4 v = make_float4(stage[row * 132 + c4],     stage[row * 132 + c4 + 1],
                               stage[row * 132 + c4 + 2], stage[row * 132 + c4 + 3]);
        *(float4*)(g_PQ + (size_t)(tB + row) * 128 + c4) = v;
    }
}

// ======================= aggregation =======================
__global__ __launch_bounds__(256) void agg_kernel(
    const float* __restrict__ h_in, const float* __restrict__ bM)
{
    int v = blockIdx.x * 8 + (threadIdx.x >> 5);
    int lane = threadIdx.x & 31;
    if (v >= NN) return;
    int beg = g_rowptr[v], end = g_rowptr[v + 1];
    const float* qrow = g_PQ + (size_t)v * 128 + 64;
    float base0 = qrow[lane] + bM[lane];
    float base1 = qrow[32 + lane] + bM[32 + lane];
    float s0 = 0.f, s1 = 0.f, q0 = 0.f, q1 = 0.f;
    float mx0 = -INFINITY, mx1 = -INFINITY, mn0 = INFINITY, mn1 = INFINITY;
    for (int p = beg; p < end; p++) {
        int s = g_srcsorted[p];
        const float* pr = g_PQ + (size_t)s * 128;
        float m0 = pr[lane] + base0;
        float m1 = pr[32 + lane] + base1;
        s0 += m0; q0 += m0 * m0; mx0 = fmaxf(mx0, m0); mn0 = fminf(mn0, m0);
        s1 += m1; q1 += m1 * m1; mx1 = fmaxf(mx1, m1); mn1 = fminf(mn1, m1);
    }
    float deg = (float)(end - beg);
    float denom = fmaxf(deg, 1.f);
    float inv = 1.f / denom;
    float mean0 = s0 * inv, mean1 = s1 * inv;
    float var0 = fmaxf(q0 * inv - mean0 * mean0, 0.f);
    float var1 = fmaxf(q1 * inv - mean1 * mean1, 0.f);
    float std0 = sqrtf(var0 + 1e-30f);
    float std1 = sqrtf(var1 + 1e-30f);
    if (end == beg) { mx0 = mx1 = 0.f; mn0 = mn1 = 0.f; }
    float* xr = g_X + (size_t)v * 448;
    xr[lane] = mean0;        xr[32 + lane] = mean1;
    xr[64 + lane] = mx0;     xr[96 + lane] = mx1;
    xr[128 + lane] = mn0;    xr[160 + lane] = mn1;
    xr[192 + lane] = std0;   xr[224 + lane] = std1;
    xr[256 + lane] = var0;   xr[288 + lane] = var1;
    xr[320 + lane] = s0;     xr[352 + lane] = s1;
    xr[384 + lane] = h_in[(size_t)v * 64 + lane];
    xr[416 + lane] = h_in[(size_t)v * 64 + 32 + lane];
    if (lane == 0) {
        float logD = logf(deg + 1.f);
        g_scal[2 * v]     = logD * (1.f / DELTA_F);
        g_scal[2 * v + 1] = (logD > 0.f) ? (DELTA_F / logD) : 0.f;
    }
}

// ======================= Z MMA + fused combine + BN1 stats =======================
// Z[*,192] = X[*,448] @ Bz[448,192]; hu = (Z0 + amp*Z1 + att*Z2 + bU)*SNORM
#define ZS_AH 0
#define ZS_AL 18432
#define ZS_BH 36864
#define ZS_BL 62464
#define ZS_BU 88064
#define Z_SMEM 88320

__global__ __launch_bounds__(256) void zmma_kernel(const float* __restrict__ bU)
{
    extern __shared__ char dsm[];
    uint32_t sb = smem_u32(dsm);
    int tid = threadIdx.x, w = tid >> 5, l = tid & 31, g = l >> 2, t = l & 3;
    int tB = blockIdx.x * 128;
    if (tid < 64) ((float*)(dsm + ZS_BU))[tid] = bU[tid];

    float c[96];
#pragma unroll
    for (int i = 0; i < 96; i++) c[i] = 0.f;

    uint32_t aAoff = (uint32_t)(w * 16 + (l & 15)) * 144 + (uint32_t)(l >> 4) * 16;
    uint32_t aBoff = (uint32_t)(l & 15) * 400 + (uint32_t)(l >> 4) * 16;

    for (int ch = 0; ch < 7; ch++) {
        // A chunk [128,64] fp32 -> bf16 hi/lo (padded X rows are zero)
        const float* Xb = g_X + (size_t)tB * 448 + ch * 64;
        for (int i = tid; i < 4096; i += 256) {
            int row = i >> 5, c2 = i & 31;
            float2 v = *(const float2*)(Xb + (size_t)row * 448 + c2 * 2);
            uint32_t u0 = __float_as_uint(v.x), u1 = __float_as_uint(v.y);
            uint32_t hi2 = __byte_perm(u0, u1, 0x7632);
            float lo0 = v.x - __uint_as_float(u0 & 0xFFFF0000u);
            float lo1 = v.y - __uint_as_float(u1 & 0xFFFF0000u);
            __nv_bfloat162 lp = __floats2bfloat162_rn(lo0, lo1);
            *(uint32_t*)(dsm + ZS_AH + row * 144 + c2 * 4) = hi2;
            *(uint32_t*)(dsm + ZS_AL + row * 144 + c2 * 4) = *(uint32_t*)&lp;
        }
        // B chunk [64][96] uint32 pairs
        const uint32_t* Bh = g_BzKh + (size_t)ch * 64 * 96;
        const uint32_t* Bl = g_BzKl + (size_t)ch * 64 * 96;
        for (int i = tid; i < 6144; i += 256) {
            int kr = i / 96, n2 = i - kr * 96;
            uint32_t off = kr * 400 + n2 * 4;
            *(uint32_t*)(dsm + ZS_BH + off) = Bh[i];
            *(uint32_t*)(dsm + ZS_BL + off) = Bl[i];
        }
        __syncthreads();
#pragma unroll
        for (int p = 0; p < 3; p++) {
            uint32_t aA = sb + (p == 2 ? ZS_AL : ZS_AH) + aAoff;
            uint32_t aB = sb + (p == 1 ? ZS_BL : ZS_BH) + aBoff;
#pragma unroll
            for (int ks = 0; ks < 4; ks++) {
                uint32_t a[4];
                ldsm4(a, aA + ks * 32);
#pragma unroll
                for (int nn = 0; nn < 12; nn++) {
                    uint32_t b[4];
                    ldsm4t(b, aB + ks * 16 * 400 + nn * 32);
                    mma16816(c + nn * 8,     a, b[0], b[1]);
                    mma16816(c + nn * 8 + 4, a, b[2], b[3]);
                }
            }
        }
        __syncthreads();
    }

    // fused combine epilogue (all thread-local: tile jj at c[jj*4]; Z0=jj 0-7, Z1=8-15, Z2=16-23)
    int r0 = w * 16 + g, r1 = r0 + 8;
    int gr0 = tB + r0, gr1 = tB + r1;
    float amp0 = g_scal[2 * gr0], att0 = g_scal[2 * gr0 + 1];
    float amp1 = g_scal[2 * gr1], att1 = g_scal[2 * gr1 + 1];
    const float* buS = (const float*)(dsm + ZS_BU);
    float* stage = (float*)dsm;   // [128][66], reuses A region (33792 B < 36864)
#pragma unroll
    for (int jj = 0; jj < 8; jj++) {
        int col = jj * 8 + 2 * t;
        float b0v = buS[col], b1v = buS[col + 1];
        stage[r0 * 66 + col]     = (c[jj*4+0] + amp0 * c[(jj+8)*4+0] + att0 * c[(jj+16)*4+0] + b0v) * SNORM;
        stage[r0 * 66 + col + 1] = (c[jj*4+1] + amp0 * c[(jj+8)*4+1] + att0 * c[(jj+16)*4+1] + b1v) * SNORM;
        stage[r1 * 66 + col]     = (c[jj*4+2] + amp1 * c[(jj+8)*4+2] + att1 * c[(jj+16)*4+2] + b0v) * SNORM;
        stage[r1 * 66 + col + 1] = (c[jj*4+3] + amp1 * c[(jj+8)*4+3] + att1 * c[(jj+16)*4+3] + b1v) * SNORM;
    }
    __syncthreads();
    // coalesced hu store
    for (int i = tid; i < 2048; i += 256) {
        int row = i >> 4, c4 = (i & 15) * 4;
        int gr = tB + row;
        if (gr < NN) {
            float4 v = make_float4(stage[row * 66 + c4],     stage[row * 66 + c4 + 1],
                                   stage[row * 66 + c4 + 2], stage[row * 66 + c4 + 3]);
            *(float4*)(g_hu + (size_t)gr * 64 + c4) = v;
        }
    }
    // BN1 stats
    {
        int ci = tid & 63, hh = tid >> 6;
        float s = 0.f, q = 0.f;
        for (int r = hh * 32; r < hh * 32 + 32; r++) {
            if (tB + r < NN) { float x = stage[r * 66 + ci]; s += x; q += x * x; }
        }
        atomicAdd(&g_stats[ci], s);
        atomicAdd(&g_stats[64 + ci], q);
    }
}

// ======================= BN1 apply + mix GEMM + residual (+ BN2 stats) =======================
__global__ __launch_bounds__(256) void mix_kernel(
    const float* __restrict__ h_in, const float* __restrict__ Wmix,
    const float* __restrict__ bmix, const float* __restrict__ gt,
    const float* __restrict__ bt)
{
    __shared__ float Wm[64 * 64];
    __shared__ float sc1[64], sh1[64];
    __shared__ float hb[8][64];
    __shared__ float ssum[8 * 64], ssq[8 * 64];
    int tid = threadIdx.x;
    for (int i = tid; i < 4096; i += 256) Wm[i] = Wmix[i];
    if (tid < 64) {
        float mu  = g_stats[tid] * (1.f / NN);
        float var = g_stats[64 + tid] * (1.f / NN) - mu * mu;
        float iv  = rsqrtf(fmaxf(var, 0.f) + EPS_BN);
        float s   = gt[tid] * iv;
        sc1[tid] = s;
        sh1[tid] = bt[tid] - mu * s;
    }
    __syncthreads();
    int w = tid >> 5, lane = tid & 31;
    float bm0 = bmix[lane], bm1 = bmix[lane + 32];
    float ls0 = 0.f, lq0 = 0.f, ls1 = 0.f, lq1 = 0.f;
    for (int row = blockIdx.x * 8 + w; row < NN; row += gridDim.x * 8) {
        float hu0 = g_hu[(size_t)row * 64 + lane];
        float hu1 = g_hu[(size_t)row * 64 + 32 + lane];
        hb[w][lane]      = hu0 * sc1[lane]      + sh1[lane];
        hb[w][lane + 32] = hu1 * sc1[lane + 32] + sh1[lane + 32];
        __syncwarp();
        float a0 = bm0, a1 = bm1;
#pragma unroll
        for (int k = 0; k < 64; k++) {
            float x = hb[w][k];
            a0 += x * Wm[k * 64 + lane];
            a1 += x * Wm[k * 64 + 32 + lane];
        }
        __syncwarp();
        float m0 = (a0 > 0.f) ? a0 : 0.01f * a0;
        float m1 = (a1 > 0.f) ? a1 : 0.01f * a1;
        float o0 = m0 + h_in[(size_t)row * 64 + lane];
        float o1 = m1 + h_in[(size_t)row * 64 + 32 + lane];
        g_ot[(size_t)row * 64 + lane]      = o0;
        g_ot[(size_t)row * 64 + 32 + lane] = o1;
        ls0 += o0; lq0 += o0 * o0;
        ls1 += o1; lq1 += o1 * o1;
    }
    ssum[w * 64 + lane] = ls0; ssum[w * 64 + 32 + lane] = ls1;
    ssq [w * 64 + lane] = lq0; ssq [w * 64 + 32 + lane] = lq1;
    __syncthreads();
    if (tid < 64) {
        float s = 0.f, q = 0.f;
#pragma unroll
        for (int i = 0; i < 8; i++) { s += ssum[i * 64 + tid]; q += ssq[i * 64 + tid]; }
        atomicAdd(&g_stats[128 + tid], s);
        atomicAdd(&g_stats[192 + tid], q);
    }
}

// ======================= BN2 apply + relu + outer residual =======================
__global__ void final_kernel(const float* __restrict__ h_in,
                             const float* __restrict__ go,
                             const float* __restrict__ bo,
                             float* __restrict__ h_out)
{
    int idx = blockIdx.x * blockDim.x + threadIdx.x;
    if (idx >= NN * 64) return;
    int c = idx & 63;
    float mu  = g_stats[128 + c] * (1.f / NN);
    float var = g_stats[192 + c] * (1.f / NN) - mu * mu;
    float iv  = rsqrtf(fmaxf(var, 0.f) + EPS_BN);
    float v = (g_ot[idx] - mu) * iv * go[c] + bo[c];
    h_out[idx] = fmaxf(v, 0.f) + h_in[idx];
}

// ======================= host =======================
extern "C" void kernel_launch(void* const* d_in, const int* in_sizes, int n_in,
                              void* d_out, int out_size)
{
    (void)in_sizes; (void)n_in; (void)out_size;
    const float* node_feat = (const float*)d_in[0];
    const int*   esrc = (const int*)d_in[2];
    const int*   edst = (const int*)d_in[3];
    const float* WM   = (const float*)d_in[4];
    const float* bM   = (const float*)d_in[5];
    const float* WU   = (const float*)d_in[6];
    const float* bU   = (const float*)d_in[7];
    const float* gt   = (const float*)d_in[8];
    const float* bt   = (const float*)d_in[9];
    const float* Wmix = (const float*)d_in[10];
    const float* bmix = (const float*)d_in[11];
    const float* go   = (const float*)d_in[12];
    const float* bo   = (const float*)d_in[13];
    float* out = (float*)d_out;

    cudaFuncSetAttribute(zmma_kernel, cudaFuncAttributeMaxDynamicSharedMemorySize, Z_SMEM);
    cudaFuncSetAttribute(pqmma_kernel, cudaFuncAttributeMaxDynamicSharedMemorySize, P_SMEM);

    float *phA, *phB;
    cudaGetSymbolAddress((void**)&phA, g_hA);
    cudaGetSymbolAddress((void**)&phB, g_hB);

    // CSR build (reused by all 4 layers)
    zero_deg_kernel<<<(NN + 255) / 256, 256>>>();
    hist_kernel<<<(NE + 255) / 256, 256>>>(edst);
    scan_kernel<<<1, 1024>>>();
    scatter_kernel<<<(NE + 255) / 256, 256>>>(esrc, edst);

    const float* h_in = node_feat;
    float* hs[2] = { phA, phB };
    for (int l = 0; l < 4; l++) {
        zero_stats_kernel<<<1, 256>>>();
        prepack_pq_kernel<<<16, 256>>>(WM + (size_t)l * 128 * 64);
        prepack_z_kernel<<<(448 * 96 + 255) / 256, 256>>>(WU + (size_t)l * 1216 * 64);
        // PQ = h @ [WM_top | WM_bot]  (mma.sync bf16, hi/lo 3-pass)
        pqmma_kernel<<<NTILES, 256, P_SMEM>>>(h_in);
        // aggregation (msg = P[src] + Q[dst] + bM, never materialized)
        agg_kernel<<<(NN + 7) / 8, 256>>>(h_in, bM + l * 64);
        // Z = [agg | h] @ Bz + fused combine/BN1-stats (mma.sync bf16)
        zmma_kernel<<<NTILES, 256, Z_SMEM>>>(bU + l * 64);
        mix_kernel<<<782, 256>>>(h_in, Wmix + (size_t)l * 64 * 64, bmix + l * 64,
                                 gt + l * 64, bt + l * 64);
        float* h_out = (l == 3) ? out : hs[l & 1];
        final_kernel<<<(NN * 64 + 255) / 256, 256>>>(h_in, go + l * 64, bo + l * 64, h_out);
        h_in = h_out;
    }
}

// round 7
// speedup vs baseline: 1.8515x; 1.4728x over previous
#include <cuda_runtime.h>
#include <cuda_bf16.h>
#include <math.h>
#include <stdint.h>

#define NN 50000
#define NPAD 50048              // 391 * 128
#define NE 500000
#define EPS_BN 1e-5f
#define SNORM 0.0044721359549995794f   // 1/sqrt(50000)
#define DELTA_F 2.5f
#define NTILES 391

// ======================= helpers =======================
__device__ __forceinline__ uint32_t smem_u32(const void* p) {
    uint32_t a;
    asm("{ .reg .u64 t; cvta.to.shared.u64 t, %1; cvt.u32.u64 %0, t; }" : "=r"(a) : "l"(p));
    return a;
}
__device__ __forceinline__ void ldsm4(uint32_t a[4], uint32_t addr) {
    asm volatile("ldmatrix.sync.aligned.m8n8.x4.shared.b16 {%0,%1,%2,%3}, [%4];"
                 : "=r"(a[0]), "=r"(a[1]), "=r"(a[2]), "=r"(a[3]) : "r"(addr));
}
__device__ __forceinline__ void ldsm4t(uint32_t a[4], uint32_t addr) {
    asm volatile("ldmatrix.sync.aligned.m8n8.x4.trans.shared.b16 {%0,%1,%2,%3}, [%4];"
                 : "=r"(a[0]), "=r"(a[1]), "=r"(a[2]), "=r"(a[3]) : "r"(addr));
}
__device__ __forceinline__ void mma16816(float* c, const uint32_t a[4],
                                         uint32_t b0, uint32_t b1) {
    asm volatile("mma.sync.aligned.m16n8k16.row.col.f32.bf16.bf16.f32 "
        "{%0,%1,%2,%3}, {%4,%5,%6,%7}, {%8,%9}, {%0,%1,%2,%3};"
        : "+f"(c[0]), "+f"(c[1]), "+f"(c[2]), "+f"(c[3])
        : "r"(a[0]), "r"(a[1]), "r"(a[2]), "r"(a[3]), "r"(b0), "r"(b1));
}
#define CP16(dst, src) \
    asm volatile("cp.async.cg.shared.global [%0], [%1], 16;" :: "r"(dst), "l"(src))
#define CP_COMMIT() asm volatile("cp.async.commit_group;")
#define CP_WAIT(n)  asm volatile("cp.async.wait_group %0;" :: "n"(n))

__device__ __forceinline__ void split_pack(float v0, float v1, uint32_t& uh, uint32_t& ul) {
    __nv_bfloat162 hp, lp;
    hp.x = __float2bfloat16(v0); hp.y = __float2bfloat16(v1);
    lp.x = __float2bfloat16(v0 - __bfloat162float(hp.x));
    lp.y = __float2bfloat16(v1 - __bfloat162float(hp.y));
    uh = *(uint32_t*)&hp; ul = *(uint32_t*)&lp;
}

// ======================= scratch (device globals) =======================
__device__ float g_PQ[(size_t)NPAD * 128];     // [P(64) | Q(64)] per node
__device__ uint32_t g_Xh[(size_t)NPAD * 224];  // X bf16 hi, packed pairs; padded rows stay 0
__device__ uint32_t g_Xl[(size_t)NPAD * 224];  // X bf16 lo
__device__ uint32_t g_hH[(size_t)NPAD * 32];   // h bf16 hi pairs
__device__ uint32_t g_hL[(size_t)NPAD * 32];   // h bf16 lo pairs
__device__ float g_hu[(size_t)NN * 64];
__device__ float g_ot[(size_t)NN * 64];
__device__ float g_hA[(size_t)NN * 64];
__device__ float g_hB[(size_t)NN * 64];
__device__ float g_scal[(size_t)NPAD * 2];     // amp, att (padded rows stay 0)
__device__ int   g_deg[NN];
__device__ int   g_rowptr[NN + 1];
__device__ int   g_cursor[NN];
__device__ int   g_srcsorted[NE];
__device__ uint32_t g_BzKh[448 * 96];          // Bz [448][192] bf16 hi, K-major, n-pairs
__device__ uint32_t g_BzKl[448 * 96];
__device__ uint32_t g_BpqKh[64 * 64];          // Bpq [64][128] bf16 hi, K-major, n-pairs
__device__ uint32_t g_BpqKl[64 * 64];
__device__ float g_stats[256];                 // BN1 sum/sq, BN2 sum/sq

// ======================= CSR build =======================
__global__ void zero_deg_kernel() {
    int i = blockIdx.x * blockDim.x + threadIdx.x;
    if (i < NN) g_deg[i] = 0;
}
__global__ void hist_kernel(const int* __restrict__ dst) {
    int e = blockIdx.x * blockDim.x + threadIdx.x;
    if (e < NE) atomicAdd(&g_deg[dst[e]], 1);
}
__global__ void scan_kernel() {
    __shared__ int sh[1024];
    int tid = threadIdx.x;
    int carry = 0;
    for (int base = 0; base < NN; base += 1024) {
        int i = base + tid;
        int v = (i < NN) ? g_deg[i] : 0;
        sh[tid] = v;
        __syncthreads();
        for (int off = 1; off < 1024; off <<= 1) {
            int t = (tid >= off) ? sh[tid - off] : 0;
            __syncthreads();
            sh[tid] += t;
            __syncthreads();
        }
        if (i < NN) {
            int incl = carry + sh[tid];
            g_rowptr[i + 1] = incl;
            g_cursor[i] = incl - v;
            if (i == 0) g_rowptr[0] = 0;
        }
        carry += sh[1023];
        __syncthreads();
    }
}
__global__ void scatter_kernel(const int* __restrict__ src, const int* __restrict__ dst) {
    int e = blockIdx.x * blockDim.x + threadIdx.x;
    if (e < NE) {
        int p = atomicAdd(&g_cursor[dst[e]], 1);
        g_srcsorted[p] = src[e];
    }
}

// ======================= weight / h prepack =======================
__global__ void zero_stats_kernel() { g_stats[threadIdx.x] = 0.f; }

__global__ void packh_kernel(const float* __restrict__ h) {
    int i = blockIdx.x * 256 + threadIdx.x;
    if (i >= NN * 32) return;
    float2 v = *(const float2*)(h + (size_t)i * 2);
    uint32_t uh, ul; split_pack(v.x, v.y, uh, ul);
    g_hH[i] = uh; g_hL[i] = ul;
}

__global__ void prepack_pq_kernel(const float* __restrict__ WM) {
    int idx = blockIdx.x * 256 + threadIdx.x;
    if (idx >= 64 * 64) return;
    int k = idx >> 6, n2 = idx & 63;
    float v[2];
#pragma unroll
    for (int j = 0; j < 2; j++) {
        int n = n2 * 2 + j;
        v[j] = (n < 64) ? WM[k * 64 + n] : WM[(64 + k) * 64 + (n - 64)];
    }
    uint32_t uh, ul; split_pack(v[0], v[1], uh, ul);
    g_BpqKh[idx] = uh; g_BpqKl[idx] = ul;
}

__global__ void prepack_z_kernel(const float* __restrict__ WU) {
    int idx = blockIdx.x * 256 + threadIdx.x;
    if (idx >= 448 * 96) return;
    int k = idx / 96, n2 = idx - k * 96;
    float v[2];
#pragma unroll
    for (int j = 0; j < 2; j++) {
        int n = n2 * 2 + j;
        float val;
        if (k < 384) {
            int b = n >> 6;
            int wrow = ((b == 0) ? 64 : (b == 1) ? 448 : 832) + k;
            val = WU[wrow * 64 + (n & 63)];
        } else {
            val = (n < 64) ? WU[(k - 384) * 64 + n] : 0.f;
        }
        v[j] = val;
    }
    uint32_t uh, ul; split_pack(v[0], v[1], uh, ul);
    g_BzKh[idx] = uh; g_BzKl[idx] = ul;
}

// ======================= PQ MMA: PQ[NPAD,128] = h[*,64] @ Bpq[64,128] =======================
#define PS_AH 0
#define PS_AL 18432
#define PS_BH 36864
#define PS_BL 54272
#define P_SMEM 71680

__global__ __launch_bounds__(256) void pqmma_kernel()
{
    extern __shared__ char dsm[];
    uint32_t sb = smem_u32(dsm);
    int tid = threadIdx.x, w = tid >> 5, l = tid & 31, g = l >> 2, t = l & 3;
    int tB = blockIdx.x * 128;

    // async loads: A 128 rows x 8 chunks, B 64 rows x 16 chunks (hi+lo each)
    for (int i = tid; i < 1024; i += 256) {
        int r = i >> 3, j = i & 7;
        uint32_t d = (uint32_t)(r * 144 + j * 16);
        const uint32_t* sh_ = g_hH + (size_t)(tB + r) * 32 + j * 4;
        const uint32_t* sl_ = g_hL + (size_t)(tB + r) * 32 + j * 4;
        CP16(sb + PS_AH + d, sh_);
        CP16(sb + PS_AL + d, sl_);
    }
    for (int i = tid; i < 1024; i += 256) {
        int kr = i >> 4, j = i & 15;
        uint32_t d = (uint32_t)(kr * 272 + j * 16);
        CP16(sb + PS_BH + d, g_BpqKh + kr * 64 + j * 4);
        CP16(sb + PS_BL + d, g_BpqKl + kr * 64 + j * 4);
    }
    CP_COMMIT();

    float c[64];
#pragma unroll
    for (int i = 0; i < 64; i++) c[i] = 0.f;

    CP_WAIT(0);
    __syncthreads();

    uint32_t aAoff = (uint32_t)(w * 16 + (l & 15)) * 144 + (uint32_t)(l >> 4) * 16;
    uint32_t aBoff = (uint32_t)(l & 15) * 272 + (uint32_t)(l >> 4) * 16;
    uint32_t aAh = sb + PS_AH + aAoff, aAl = sb + PS_AL + aAoff;
    uint32_t aBh = sb + PS_BH + aBoff, aBl = sb + PS_BL + aBoff;
#pragma unroll
    for (int ks = 0; ks < 4; ks++) {
        uint32_t ah[4], al[4];
        ldsm4(ah, aAh + ks * 32);
        ldsm4(al, aAl + ks * 32);
#pragma unroll
        for (int nn = 0; nn < 8; nn++) {
            uint32_t bh[4], bl[4];
            ldsm4t(bh, aBh + ks * 16 * 272 + nn * 32);
            ldsm4t(bl, aBl + ks * 16 * 272 + nn * 32);
            mma16816(c + nn * 8,     ah, bh[0], bh[1]);
            mma16816(c + nn * 8 + 4, ah, bh[2], bh[3]);
            mma16816(c + nn * 8,     ah, bl[0], bl[1]);
            mma16816(c + nn * 8 + 4, ah, bl[2], bl[3]);
            mma16816(c + nn * 8,     al, bh[0], bh[1]);
            mma16816(c + nn * 8 + 4, al, bh[2], bh[3]);
        }
    }
    __syncthreads();

    // stage [128][132] then coalesced store
    float* stage = (float*)dsm;
    int r0 = w * 16 + g, r1 = r0 + 8;
#pragma unroll
    for (int jj = 0; jj < 16; jj++) {
        int col = jj * 8 + 2 * t;
        stage[r0 * 132 + col]     = c[jj * 4 + 0];
        stage[r0 * 132 + col + 1] = c[jj * 4 + 1];
        stage[r1 * 132 + col]     = c[jj * 4 + 2];
        stage[r1 * 132 + col + 1] = c[jj * 4 + 3];
    }
    __syncthreads();
    for (int i = tid; i < 4096; i += 256) {
        int row = i >> 5, c4 = (i & 31) * 4;
        float4 v = make_float4(stage[row * 132 + c4],     stage[row * 132 + c4 + 1],
                               stage[row * 132 + c4 + 2], stage[row * 132 + c4 + 3]);
        *(float4*)(g_PQ + (size_t)(tB + row) * 128 + c4) = v;
    }
}

// ======================= aggregation -> packed bf16 X =======================
// lane owns column pair (2l, 2l+1) of each 64-col group
__global__ __launch_bounds__(256) void agg_kernel(const float* __restrict__ bM)
{
    int v = blockIdx.x * 8 + (threadIdx.x >> 5);
    int lane = threadIdx.x & 31;
    if (v >= NN) return;
    int beg = g_rowptr[v], end = g_rowptr[v + 1];
    int c0 = 2 * lane;
    const float* qrow = g_PQ + (size_t)v * 128 + 64;
    float2 qv = *(const float2*)(qrow + c0);
    float2 bv = *(const float2*)(bM + c0);
    float base0 = qv.x + bv.x;
    float base1 = qv.y + bv.y;
    float s0 = 0.f, s1 = 0.f, q0 = 0.f, q1 = 0.f;
    float mx0 = -INFINITY, mx1 = -INFINITY, mn0 = INFINITY, mn1 = INFINITY;
    for (int p = beg; p < end; p++) {
        int s = g_srcsorted[p];
        float2 pv = *(const float2*)(g_PQ + (size_t)s * 128 + c0);
        float m0 = pv.x + base0;
        float m1 = pv.y + base1;
        s0 += m0; q0 += m0 * m0; mx0 = fmaxf(mx0, m0); mn0 = fminf(mn0, m0);
        s1 += m1; q1 += m1 * m1; mx1 = fmaxf(mx1, m1); mn1 = fminf(mn1, m1);
    }
    float deg = (float)(end - beg);
    float denom = fmaxf(deg, 1.f);
    float inv = 1.f / denom;
    float mean0 = s0 * inv, mean1 = s1 * inv;
    float var0 = fmaxf(q0 * inv - mean0 * mean0, 0.f);
    float var1 = fmaxf(q1 * inv - mean1 * mean1, 0.f);
    float std0 = sqrtf(var0 + 1e-30f);
    float std1 = sqrtf(var1 + 1e-30f);
    if (end == beg) { mx0 = mx1 = 0.f; mn0 = mn1 = 0.f; }
    uint32_t* xh = g_Xh + (size_t)v * 224;
    uint32_t* xl = g_Xl + (size_t)v * 224;
    uint32_t uh, ul;
    split_pack(mean0, mean1, uh, ul); xh[lane] = uh;        xl[lane] = ul;
    split_pack(mx0, mx1, uh, ul);     xh[32 + lane] = uh;   xl[32 + lane] = ul;
    split_pack(mn0, mn1, uh, ul);     xh[64 + lane] = uh;   xl[64 + lane] = ul;
    split_pack(std0, std1, uh, ul);   xh[96 + lane] = uh;   xl[96 + lane] = ul;
    split_pack(var0, var1, uh, ul);   xh[128 + lane] = uh;  xl[128 + lane] = ul;
    split_pack(s0, s1, uh, ul);       xh[160 + lane] = uh;  xl[160 + lane] = ul;
    xh[192 + lane] = g_hH[(size_t)v * 32 + lane];
    xl[192 + lane] = g_hL[(size_t)v * 32 + lane];
    if (lane == 0) {
        float logD = logf(deg + 1.f);
        g_scal[2 * v]     = logD * (1.f / DELTA_F);
        g_scal[2 * v + 1] = (logD > 0.f) ? (DELTA_F / logD) : 0.f;
    }
}

// ======================= Z MMA (double-buffered cp.async) + fused combine + BN1 stats ===
// Z[*,192] = X[*,448] @ Bz[448,192]; hu = (Z0 + amp*Z1 + att*Z2 + bU)*SNORM
#define ZS_AH 0
#define ZS_AL 18432
#define ZS_BH 36864
#define ZS_BL 62464
#define Z_STAGE 88064
#define ZS_BU (2 * Z_STAGE)
#define Z_SMEM (2 * Z_STAGE + 256)

__global__ __launch_bounds__(256) void zmma_kernel(const float* __restrict__ bU)
{
    extern __shared__ char dsm[];
    uint32_t sb = smem_u32(dsm);
    int tid = threadIdx.x, w = tid >> 5, l = tid & 31, g = l >> 2, t = l & 3;
    int tB = blockIdx.x * 128;
    if (tid < 64) ((float*)(dsm + ZS_BU))[tid] = bU[tid];

    float c[96];
#pragma unroll
    for (int i = 0; i < 96; i++) c[i] = 0.f;

    uint32_t aAoff = (uint32_t)(w * 16 + (l & 15)) * 144 + (uint32_t)(l >> 4) * 16;
    uint32_t aBoff = (uint32_t)(l & 15) * 400 + (uint32_t)(l >> 4) * 16;

    // prefetch chunk 0
    {
        uint32_t bs = sb;
        for (int i = tid; i < 1024; i += 256) {
            int r = i >> 3, j = i & 7;
            uint32_t d = (uint32_t)(r * 144 + j * 16);
            CP16(bs + ZS_AH + d, g_Xh + (size_t)(tB + r) * 224 + j * 4);
            CP16(bs + ZS_AL + d, g_Xl + (size_t)(tB + r) * 224 + j * 4);
        }
        for (int i = tid; i < 1536; i += 256) {
            int kr = i / 24, j = i - kr * 24;
            uint32_t d = (uint32_t)(kr * 400 + j * 16);
            CP16(bs + ZS_BH + d, g_BzKh + kr * 96 + j * 4);
            CP16(bs + ZS_BL + d, g_BzKl + kr * 96 + j * 4);
        }
        CP_COMMIT();
    }

    for (int ch = 0; ch < 7; ch++) {
        if (ch < 6) {
            // prefetch chunk ch+1 into the other buffer
            uint32_t bs = sb + ((ch + 1) & 1) * Z_STAGE;
            int kc = (ch + 1) * 32;   // uint32 pair offset in X row
            const uint32_t* Bh = g_BzKh + (size_t)(ch + 1) * 6144;
            const uint32_t* Bl = g_BzKl + (size_t)(ch + 1) * 6144;
            for (int i = tid; i < 1024; i += 256) {
                int r = i >> 3, j = i & 7;
                uint32_t d = (uint32_t)(r * 144 + j * 16);
                CP16(bs + ZS_AH + d, g_Xh + (size_t)(tB + r) * 224 + kc + j * 4);
                CP16(bs + ZS_AL + d, g_Xl + (size_t)(tB + r) * 224 + kc + j * 4);
            }
            for (int i = tid; i < 1536; i += 256) {
                int kr = i / 24, j = i - kr * 24;
                uint32_t d = (uint32_t)(kr * 400 + j * 16);
                CP16(bs + ZS_BH + d, Bh + kr * 96 + j * 4);
                CP16(bs + ZS_BL + d, Bl + kr * 96 + j * 4);
            }
            CP_COMMIT();
            CP_WAIT(1);
        } else {
            CP_WAIT(0);
        }
        __syncthreads();

        uint32_t bufOff = (ch & 1) * Z_STAGE;
        uint32_t aAh = sb + bufOff + ZS_AH + aAoff, aAl = sb + bufOff + ZS_AL + aAoff;
        uint32_t aBh = sb + bufOff + ZS_BH + aBoff, aBl = sb + bufOff + ZS_BL + aBoff;
#pragma unroll
        for (int ks = 0; ks < 4; ks++) {
            uint32_t ah[4], al[4];
            ldsm4(ah, aAh + ks * 32);
            ldsm4(al, aAl + ks * 32);
#pragma unroll
            for (int nn = 0; nn < 12; nn++) {
                uint32_t bh[4], bl[4];
                ldsm4t(bh, aBh + ks * 16 * 400 + nn * 32);
                ldsm4t(bl, aBl + ks * 16 * 400 + nn * 32);
                mma16816(c + nn * 8,     ah, bh[0], bh[1]);
                mma16816(c + nn * 8 + 4, ah, bh[2], bh[3]);
                mma16816(c + nn * 8,     ah, bl[0], bl[1]);
                mma16816(c + nn * 8 + 4, ah, bl[2], bl[3]);
                mma16816(c + nn * 8,     al, bh[0], bh[1]);
                mma16816(c + nn * 8 + 4, al, bh[2], bh[3]);
            }
        }
        __syncthreads();
    }

    // fused combine epilogue (thread-local: tile jj at c[jj*4]; Z0=jj 0-7, Z1=8-15, Z2=16-23)
    int r0 = w * 16 + g, r1 = r0 + 8;
    int gr0 = tB + r0, gr1 = tB + r1;
    float amp0 = g_scal[2 * gr0], att0 = g_scal[2 * gr0 + 1];
    float amp1 = g_scal[2 * gr1], att1 = g_scal[2 * gr1 + 1];
    const float* buS = (const float*)(dsm + ZS_BU);
    float* stage = (float*)dsm;   // [128][66] = 33792 B, fits in stage-0 A region
#pragma unroll
    for (int jj = 0; jj < 8; jj++) {
        int col = jj * 8 + 2 * t;
        float b0v = buS[col], b1v = buS[col + 1];
        stage[r0 * 66 + col]     = (c[jj*4+0] + amp0 * c[(jj+8)*4+0] + att0 * c[(jj+16)*4+0] + b0v) * SNORM;
        stage[r0 * 66 + col + 1] = (c[jj*4+1] + amp0 * c[(jj+8)*4+1] + att0 * c[(jj+16)*4+1] + b1v) * SNORM;
        stage[r1 * 66 + col]     = (c[jj*4+2] + amp1 * c[(jj+8)*4+2] + att1 * c[(jj+16)*4+2] + b0v) * SNORM;
        stage[r1 * 66 + col + 1] = (c[jj*4+3] + amp1 * c[(jj+8)*4+3] + att1 * c[(jj+16)*4+3] + b1v) * SNORM;
    }
    __syncthreads();
    for (int i = tid; i < 2048; i += 256) {
        int row = i >> 4, c4 = (i & 15) * 4;
        int gr = tB + row;
        if (gr < NN) {
            float4 v = make_float4(stage[row * 66 + c4],     stage[row * 66 + c4 + 1],
                                   stage[row * 66 + c4 + 2], stage[row * 66 + c4 + 3]);
            *(float4*)(g_hu + (size_t)gr * 64 + c4) = v;
        }
    }
    {
        int ci = tid & 63, hh = tid >> 6;
        float s = 0.f, q = 0.f;
        for (int r = hh * 32; r < hh * 32 + 32; r++) {
            if (tB + r < NN) { float x = stage[r * 66 + ci]; s += x; q += x * x; }
        }
        atomicAdd(&g_stats[ci], s);
        atomicAdd(&g_stats[64 + ci], q);
    }
}

// ======================= BN1 apply + mix GEMM + residual (+ BN2 stats) =======================
__global__ __launch_bounds__(256) void mix_kernel(
    const float* __restrict__ h_in, const float* __restrict__ Wmix,
    const float* __restrict__ bmix, const float* __restrict__ gt,
    const float* __restrict__ bt)
{
    __shared__ float Wm[64 * 64];
    __shared__ float sc1[64], sh1[64];
    __shared__ float hb[8][64];
    __shared__ float ssum[8 * 64], ssq[8 * 64];
    int tid = threadIdx.x;
    for (int i = tid; i < 4096; i += 256) Wm[i] = Wmix[i];
    if (tid < 64) {
        float mu  = g_stats[tid] * (1.f / NN);
        float var = g_stats[64 + tid] * (1.f / NN) - mu * mu;
        float iv  = rsqrtf(fmaxf(var, 0.f) + EPS_BN);
        float s   = gt[tid] * iv;
        sc1[tid] = s;
        sh1[tid] = bt[tid] - mu * s;
    }
    __syncthreads();
    int w = tid >> 5, lane = tid & 31;
    float bm0 = bmix[lane], bm1 = bmix[lane + 32];
    float ls0 = 0.f, lq0 = 0.f, ls1 = 0.f, lq1 = 0.f;
    for (int row = blockIdx.x * 8 + w; row < NN; row += gridDim.x * 8) {
        float hu0 = g_hu[(size_t)row * 64 + lane];
        float hu1 = g_hu[(size_t)row * 64 + 32 + lane];
        hb[w][lane]      = hu0 * sc1[lane]      + sh1[lane];
        hb[w][lane + 32] = hu1 * sc1[lane + 32] + sh1[lane + 32];
        __syncwarp();
        float a0 = bm0, a1 = bm1;
#pragma unroll
        for (int k = 0; k < 64; k++) {
            float x = hb[w][k];
            a0 += x * Wm[k * 64 + lane];
            a1 += x * Wm[k * 64 + 32 + lane];
        }
        __syncwarp();
        float m0 = (a0 > 0.f) ? a0 : 0.01f * a0;
        float m1 = (a1 > 0.f) ? a1 : 0.01f * a1;
        float o0 = m0 + h_in[(size_t)row * 64 + lane];
        float o1 = m1 + h_in[(size_t)row * 64 + 32 + lane];
        g_ot[(size_t)row * 64 + lane]      = o0;
        g_ot[(size_t)row * 64 + 32 + lane] = o1;
        ls0 += o0; lq0 += o0 * o0;
        ls1 += o1; lq1 += o1 * o1;
    }
    ssum[w * 64 + lane] = ls0; ssum[w * 64 + 32 + lane] = ls1;
    ssq [w * 64 + lane] = lq0; ssq [w * 64 + 32 + lane] = lq1;
    __syncthreads();
    if (tid < 64) {
        float s = 0.f, q = 0.f;
#pragma unroll
        for (int i = 0; i < 8; i++) { s += ssum[i * 64 + tid]; q += ssq[i * 64 + tid]; }
        atomicAdd(&g_stats[128 + tid], s);
        atomicAdd(&g_stats[192 + tid], q);
    }
}

// ======================= BN2 apply + relu + outer residual (+ packed h for next layer) ====
__global__ void final_kernel(const float* __restrict__ h_in,
                             const float* __restrict__ go,
                             const float* __restrict__ bo,
                             float* __restrict__ h_out,
                             int writePacked)
{
    int i = blockIdx.x * blockDim.x + threadIdx.x;
    if (i >= NN * 32) return;
    int p = i & 31;
    int c0 = 2 * p;
    float mu0  = g_stats[128 + c0] * (1.f / NN);
    float mu1  = g_stats[128 + c0 + 1] * (1.f / NN);
    float var0 = g_stats[192 + c0] * (1.f / NN) - mu0 * mu0;
    float var1 = g_stats[192 + c0 + 1] * (1.f / NN) - mu1 * mu1;
    float iv0  = rsqrtf(fmaxf(var0, 0.f) + EPS_BN);
    float iv1  = rsqrtf(fmaxf(var1, 0.f) + EPS_BN);
    float2 ot = *(const float2*)(g_ot + (size_t)i * 2);
    float2 hi = *(const float2*)(h_in + (size_t)i * 2);
    float v0 = fmaxf((ot.x - mu0) * iv0 * go[c0]     + bo[c0],     0.f) + hi.x;
    float v1 = fmaxf((ot.y - mu1) * iv1 * go[c0 + 1] + bo[c0 + 1], 0.f) + hi.y;
    *(float2*)(h_out + (size_t)i * 2) = make_float2(v0, v1);
    if (writePacked) {
        uint32_t uh, ul; split_pack(v0, v1, uh, ul);
        g_hH[i] = uh; g_hL[i] = ul;
    }
}

// ======================= host =======================
extern "C" void kernel_launch(void* const* d_in, const int* in_sizes, int n_in,
                              void* d_out, int out_size)
{
    (void)in_sizes; (void)n_in; (void)out_size;
    const float* node_feat = (const float*)d_in[0];
    const int*   esrc = (const int*)d_in[2];
    const int*   edst = (const int*)d_in[3];
    const float* WM   = (const float*)d_in[4];
    const float* bM   = (const float*)d_in[5];
    const float* WU   = (const float*)d_in[6];
    const float* bU   = (const float*)d_in[7];
    const float* gt   = (const float*)d_in[8];
    const float* bt   = (const float*)d_in[9];
    const float* Wmix = (const float*)d_in[10];
    const float* bmix = (const float*)d_in[11];
    const float* go   = (const float*)d_in[12];
    const float* bo   = (const float*)d_in[13];
    float* out = (float*)d_out;

    cudaFuncSetAttribute(zmma_kernel, cudaFuncAttributeMaxDynamicSharedMemorySize, Z_SMEM);
    cudaFuncSetAttribute(pqmma_kernel, cudaFuncAttributeMaxDynamicSharedMemorySize, P_SMEM);

    float *phA, *phB;
    cudaGetSymbolAddress((void**)&phA, g_hA);
    cudaGetSymbolAddress((void**)&phB, g_hB);

    // CSR build (reused by all 4 layers)
    zero_deg_kernel<<<(NN + 255) / 256, 256>>>();
    hist_kernel<<<(NE + 255) / 256, 256>>>(edst);
    scan_kernel<<<1, 1024>>>();
    scatter_kernel<<<(NE + 255) / 256, 256>>>(esrc, edst);
    packh_kernel<<<(NN * 32 + 255) / 256, 256>>>(node_feat);

    const float* h_in = node_feat;
    float* hs[2] = { phA, phB };
    for (int l = 0; l < 4; l++) {
        zero_stats_kernel<<<1, 256>>>();
        prepack_pq_kernel<<<16, 256>>>(WM + (size_t)l * 128 * 64);
        prepack_z_kernel<<<(448 * 96 + 255) / 256, 256>>>(WU + (size_t)l * 1216 * 64);
        // PQ = h @ [WM_top | WM_bot]  (mma.sync bf16 3-pass, cp.async inputs)
        pqmma_kernel<<<NTILES, 256, P_SMEM>>>();
        // aggregation -> packed bf16 X (msg = P[src] + Q[dst] + bM, never materialized)
        agg_kernel<<<(NN + 7) / 8, 256>>>(bM + l * 64);
        // Z = X @ Bz (double-buffered cp.async pipeline) + fused combine/BN1-stats
        zmma_kernel<<<NTILES, 256, Z_SMEM>>>(bU + l * 64);
        mix_kernel<<<782, 256>>>(h_in, Wmix + (size_t)l * 64 * 64, bmix + l * 64,
                                 gt + l * 64, bt + l * 64);
        float* h_out = (l == 3) ? out : hs[l & 1];
        final_kernel<<<(NN * 32 + 255) / 256, 256>>>(h_in, go + l * 64, bo + l * 64,
                                                     h_out, (l < 3) ? 1 : 0);
        h_in = h_out;
    }
}

// round 9
// speedup vs baseline: 2.1435x; 1.1577x over previous
#include <cuda_runtime.h>
#include <cuda_bf16.h>
#include <math.h>
#include <stdint.h>

#define NN 50000
#define NPAD 50048              // 391 * 128
#define NE 500000
#define EPS_BN 1e-5f
#define SNORM 0.0044721359549995794f   // 1/sqrt(50000)
#define DELTA_F 2.5f
#define NTILES 391

// ======================= helpers =======================
__device__ __forceinline__ uint32_t smem_u32(const void* p) {
    uint32_t a;
    asm("{ .reg .u64 t; cvta.to.shared.u64 t, %1; cvt.u32.u64 %0, t; }" : "=r"(a) : "l"(p));
    return a;
}
__device__ __forceinline__ void ldsm4(uint32_t a[4], uint32_t addr) {
    asm volatile("ldmatrix.sync.aligned.m8n8.x4.shared.b16 {%0,%1,%2,%3}, [%4];"
                 : "=r"(a[0]), "=r"(a[1]), "=r"(a[2]), "=r"(a[3]) : "r"(addr));
}
__device__ __forceinline__ void ldsm4t(uint32_t a[4], uint32_t addr) {
    asm volatile("ldmatrix.sync.aligned.m8n8.x4.trans.shared.b16 {%0,%1,%2,%3}, [%4];"
                 : "=r"(a[0]), "=r"(a[1]), "=r"(a[2]), "=r"(a[3]) : "r"(addr));
}
__device__ __forceinline__ void mma16816(float* c, const uint32_t a[4],
                                         uint32_t b0, uint32_t b1) {
    asm volatile("mma.sync.aligned.m16n8k16.row.col.f32.bf16.bf16.f32 "
        "{%0,%1,%2,%3}, {%4,%5,%6,%7}, {%8,%9}, {%0,%1,%2,%3};"
        : "+f"(c[0]), "+f"(c[1]), "+f"(c[2]), "+f"(c[3])
        : "r"(a[0]), "r"(a[1]), "r"(a[2]), "r"(a[3]), "r"(b0), "r"(b1));
}
#define CP16(dst, src) \
    asm volatile("cp.async.cg.shared.global [%0], [%1], 16;" :: "r"(dst), "l"(src))
#define CP_COMMIT() asm volatile("cp.async.commit_group;")
#define CP_WAIT(n)  asm volatile("cp.async.wait_group %0;" :: "n"(n))

__device__ __forceinline__ void split_pack(float v0, float v1, uint32_t& uh, uint32_t& ul) {
    __nv_bfloat162 hp, lp;
    hp.x = __float2bfloat16(v0); hp.y = __float2bfloat16(v1);
    lp.x = __float2bfloat16(v0 - __bfloat162float(hp.x));
    lp.y = __float2bfloat16(v1 - __bfloat162float(hp.y));
    uh = *(uint32_t*)&hp; ul = *(uint32_t*)&lp;
}

// ======================= scratch (device globals) =======================
__device__ float g_PQ[(size_t)NPAD * 128];     // [P(64) | Q(64)] per node
__device__ uint32_t g_Xh[(size_t)NPAD * 224];  // X bf16 hi pairs; padded rows stay 0
__device__ uint32_t g_Xl[(size_t)NPAD * 224];
__device__ uint32_t g_hH[(size_t)NPAD * 32];   // h bf16 hi pairs
__device__ uint32_t g_hL[(size_t)NPAD * 32];
__device__ uint32_t g_huH[(size_t)NPAD * 32];  // hu bf16 hi pairs
__device__ uint32_t g_huL[(size_t)NPAD * 32];
__device__ float g_ot[(size_t)NN * 64];
__device__ float g_hA[(size_t)NN * 64];
__device__ float g_hB[(size_t)NN * 64];
__device__ float g_scal[(size_t)NPAD * 2];     // amp, att (padded rows stay 0)
__device__ int   g_deg[NN];
__device__ int   g_rowptr[NN + 1];
__device__ int   g_cursor[NN];
__device__ int   g_srcsorted[NE];
__device__ uint32_t g_BzKh[4 * 448 * 96];      // per-layer Bz bf16 hi, K-major pairs
__device__ uint32_t g_BzKl[4 * 448 * 96];
__device__ uint32_t g_BpqKh[4 * 64 * 64];
__device__ uint32_t g_BpqKl[4 * 64 * 64];
__device__ float g_stats[1024];                // [layer][BN1 s, BN1 q, BN2 s, BN2 q] x 64

// ======================= CSR build =======================
__global__ void hist_kernel(const int* __restrict__ dst) {
    int e = blockIdx.x * blockDim.x + threadIdx.x;
    if (e < NE) atomicAdd(&g_deg[dst[e]], 1);
}
__global__ void scan_kernel() {
    // 1024 threads, 49 elements each, shuffle block scan
    int tid = threadIdx.x;
    int base = tid * 49;
    int sum = 0;
    for (int j = 0; j < 49; j++) {
        int i = base + j;
        if (i < NN) sum += g_deg[i];
    }
    int lane = tid & 31, wid = tid >> 5;
    int v = sum;
#pragma unroll
    for (int o = 1; o < 32; o <<= 1) {
        int t = __shfl_up_sync(0xFFFFFFFFu, v, o);
        if (lane >= o) v += t;
    }
    __shared__ int wsum[32];
    if (lane == 31) wsum[wid] = v;
    __syncthreads();
    if (wid == 0) {
        int x = wsum[lane];
#pragma unroll
        for (int o = 1; o < 32; o <<= 1) {
            int t = __shfl_up_sync(0xFFFFFFFFu, x, o);
            if (lane >= o) x += t;
        }
        wsum[lane] = x;
    }
    __syncthreads();
    int excl = v - sum + (wid > 0 ? wsum[wid - 1] : 0);
    int run = excl;
    for (int j = 0; j < 49; j++) {
        int i = base + j;
        if (i < NN) {
            int d = g_deg[i];
            g_cursor[i] = run;
            run += d;
            g_rowptr[i + 1] = run;
        }
    }
    if (tid == 0) g_rowptr[0] = 0;
}
__global__ void scatter_kernel(const int* __restrict__ src, const int* __restrict__ dst) {
    int e = blockIdx.x * blockDim.x + threadIdx.x;
    if (e < NE) {
        int p = atomicAdd(&g_cursor[dst[e]], 1);
        g_srcsorted[p] = src[e];
    }
}

// ======================= one-shot prepack: all layers' weights + stats/deg zero ==========
__global__ void prepack_all_kernel(const float* __restrict__ WM, const float* __restrict__ WU) {
    int idx = blockIdx.x * 256 + threadIdx.x;
    if (idx < 172032) {                          // Bz: 4 layers x 448 x 96 pairs
        int lyr = idx / 43008, r = idx - lyr * 43008;
        int k = r / 96, n2 = r - k * 96;
        const float* W = WU + (size_t)lyr * 1216 * 64;
        float v[2];
#pragma unroll
        for (int j = 0; j < 2; j++) {
            int n = n2 * 2 + j;
            float val;
            if (k < 384) {
                int b = n >> 6;
                int wrow = ((b == 0) ? 64 : (b == 1) ? 448 : 832) + k;
                val = W[wrow * 64 + (n & 63)];
            } else {
                val = (n < 64) ? W[(k - 384) * 64 + n] : 0.f;
            }
            v[j] = val;
        }
        uint32_t uh, ul; split_pack(v[0], v[1], uh, ul);
        g_BzKh[idx] = uh; g_BzKl[idx] = ul;
    } else if (idx < 188416) {                   // Bpq: 4 layers x 64 x 64 pairs
        int j0 = idx - 172032;
        int lyr = j0 >> 12, r = j0 & 4095;
        int k = r >> 6, n2 = r & 63;
        const float* W = WM + (size_t)lyr * 128 * 64;
        float v[2];
#pragma unroll
        for (int j = 0; j < 2; j++) {
            int n = n2 * 2 + j;
            v[j] = (n < 64) ? W[k * 64 + n] : W[(64 + k) * 64 + (n - 64)];
        }
        uint32_t uh, ul; split_pack(v[0], v[1], uh, ul);
        g_BpqKh[j0] = uh; g_BpqKl[j0] = ul;
    } else if (idx < 189440) {
        g_stats[idx - 188416] = 0.f;
    } else if (idx < 239440) {
        g_deg[idx - 189440] = 0;
    }
}

// ======================= PQ MMA (+ fused BN2/relu/residual of previous layer) ============
// mode0: A = srcO rows (fp32) packed.  mode1: A = relu(BN2(srcO)) + hprev, also -> h_out.
#define PS_AH 0
#define PS_AL 18432
#define PS_BH 36864
#define PS_BL 54272
#define PS_CONST 71680
#define P_SMEM 72192

__global__ __launch_bounds__(256) void pqmma_kernel(
    const float* __restrict__ srcO, const float* __restrict__ hprev,
    const float* __restrict__ go, const float* __restrict__ bo,
    float* __restrict__ h_out, int statsL, int bsliceL, int mode)
{
    extern __shared__ char dsm[];
    uint32_t sb = smem_u32(dsm);
    int tid = threadIdx.x, w = tid >> 5, l = tid & 31, g = l >> 2, t = l & 3;
    int tB = blockIdx.x * 128;

    // B cp.async
    const uint32_t* BKh = g_BpqKh + (size_t)bsliceL * 4096;
    const uint32_t* BKl = g_BpqKl + (size_t)bsliceL * 4096;
    for (int i = tid; i < 1024; i += 256) {
        int kr = i >> 4, j = i & 15;
        uint32_t d = (uint32_t)(kr * 272 + j * 16);
        CP16(sb + PS_BH + d, BKh + kr * 64 + j * 4);
        CP16(sb + PS_BL + d, BKl + kr * 64 + j * 4);
    }
    CP_COMMIT();

    float* cst = (float*)(dsm + PS_CONST);
    if (mode && tid < 64) {
        float mu  = g_stats[statsL * 256 + 128 + tid] * (1.f / NN);
        float var = g_stats[statsL * 256 + 192 + tid] * (1.f / NN) - mu * mu;
        float iv  = rsqrtf(fmaxf(var, 0.f) + EPS_BN);
        float s2  = iv * go[tid];
        cst[tid] = s2;
        cst[64 + tid] = bo[tid] - mu * s2;
    }
    __syncthreads();

    // A build: fused previous-layer final (mode1) or plain pack (mode0)
    for (int i = tid; i < 2048; i += 256) {
        int row = i >> 4, c4 = (i & 15) * 4, gr = tB + row;
        float4 v = make_float4(0.f, 0.f, 0.f, 0.f);
        if (gr < NN) {
            float4 o = *(const float4*)(srcO + (size_t)gr * 64 + c4);
            if (mode) {
                float4 hp = *(const float4*)(hprev + (size_t)gr * 64 + c4);
                v.x = fmaxf(o.x * cst[c4 + 0] + cst[64 + c4 + 0], 0.f) + hp.x;
                v.y = fmaxf(o.y * cst[c4 + 1] + cst[64 + c4 + 1], 0.f) + hp.y;
                v.z = fmaxf(o.z * cst[c4 + 2] + cst[64 + c4 + 2], 0.f) + hp.z;
                v.w = fmaxf(o.w * cst[c4 + 3] + cst[64 + c4 + 3], 0.f) + hp.w;
                *(float4*)(h_out + (size_t)gr * 64 + c4) = v;
            } else {
                v = o;
            }
        }
        uint32_t uh0, ul0, uh1, ul1;
        split_pack(v.x, v.y, uh0, ul0);
        split_pack(v.z, v.w, uh1, ul1);
        int pi = gr * 32 + (c4 >> 1);
        *(uint2*)(g_hH + pi) = make_uint2(uh0, uh1);
        *(uint2*)(g_hL + pi) = make_uint2(ul0, ul1);
        uint32_t soff = (uint32_t)(row * 144 + c4 * 2);
        *(uint2*)(dsm + PS_AH + soff) = make_uint2(uh0, uh1);
        *(uint2*)(dsm + PS_AL + soff) = make_uint2(ul0, ul1);
    }
    CP_WAIT(0);
    __syncthreads();

    float c[64];
#pragma unroll
    for (int i = 0; i < 64; i++) c[i] = 0.f;

    uint32_t aAoff = (uint32_t)(w * 16 + (l & 15)) * 144 + (uint32_t)(l >> 4) * 16;
    uint32_t aBoff = (uint32_t)(l & 15) * 272 + (uint32_t)(l >> 4) * 16;
    uint32_t aAh = sb + PS_AH + aAoff, aAl = sb + PS_AL + aAoff;
    uint32_t aBh = sb + PS_BH + aBoff, aBl = sb + PS_BL + aBoff;
#pragma unroll
    for (int ks = 0; ks < 4; ks++) {
        uint32_t ah[4], al[4];
        ldsm4(ah, aAh + ks * 32);
        ldsm4(al, aAl + ks * 32);
#pragma unroll
        for (int nn = 0; nn < 8; nn++) {
            uint32_t bh[4], bl[4];
            ldsm4t(bh, aBh + ks * 16 * 272 + nn * 32);
            ldsm4t(bl, aBl + ks * 16 * 272 + nn * 32);
            mma16816(c + nn * 8,     ah, bh[0], bh[1]);
            mma16816(c + nn * 8 + 4, ah, bh[2], bh[3]);
            mma16816(c + nn * 8,     ah, bl[0], bl[1]);
            mma16816(c + nn * 8 + 4, ah, bl[2], bl[3]);
            mma16816(c + nn * 8,     al, bh[0], bh[1]);
            mma16816(c + nn * 8 + 4, al, bh[2], bh[3]);
        }
    }
    __syncthreads();

    float* stage = (float*)dsm;
    int r0 = w * 16 + g, r1 = r0 + 8;
#pragma unroll
    for (int jj = 0; jj < 16; jj++) {
        int col = jj * 8 + 2 * t;
        stage[r0 * 132 + col]     = c[jj * 4 + 0];
        stage[r0 * 132 + col + 1] = c[jj * 4 + 1];
        stage[r1 * 132 + col]     = c[jj * 4 + 2];
        stage[r1 * 132 + col + 1] = c[jj * 4 + 3];
    }
    __syncthreads();
    for (int i = tid; i < 4096; i += 256) {
        int row = i >> 5, c4 = (i & 31) * 4;
        float4 v = make_float4(stage[row * 132 + c4],     stage[row * 132 + c4 + 1],
                               stage[row * 132 + c4 + 2], stage[row * 132 + c4 + 3]);
        *(float4*)(g_PQ + (size_t)(tB + row) * 128 + c4) = v;
    }
}

// ======================= aggregation -> packed bf16 X =======================
__global__ __launch_bounds__(256) void agg_kernel(const float* __restrict__ bM)
{
    int v = blockIdx.x * 8 + (threadIdx.x >> 5);
    int lane = threadIdx.x & 31;
    if (v >= NN) return;
    int beg = g_rowptr[v], end = g_rowptr[v + 1];
    int c0 = 2 * lane;
    const float* qrow = g_PQ + (size_t)v * 128 + 64;
    float2 qv = *(const float2*)(qrow + c0);
    float2 bv = *(const float2*)(bM + c0);
    float base0 = qv.x + bv.x;
    float base1 = qv.y + bv.y;
    float s0 = 0.f, s1 = 0.f, q0 = 0.f, q1 = 0.f;
    float mx0 = -INFINITY, mx1 = -INFINITY, mn0 = INFINITY, mn1 = INFINITY;
    for (int p = beg; p < end; p++) {
        int s = g_srcsorted[p];
        float2 pv = *(const float2*)(g_PQ + (size_t)s * 128 + c0);
        float m0 = pv.x + base0;
        float m1 = pv.y + base1;
        s0 += m0; q0 += m0 * m0; mx0 = fmaxf(mx0, m0); mn0 = fminf(mn0, m0);
        s1 += m1; q1 += m1 * m1; mx1 = fmaxf(mx1, m1); mn1 = fminf(mn1, m1);
    }
    float deg = (float)(end - beg);
    float denom = fmaxf(deg, 1.f);
    float inv = 1.f / denom;
    float mean0 = s0 * inv, mean1 = s1 * inv;
    float var0 = fmaxf(q0 * inv - mean0 * mean0, 0.f);
    float var1 = fmaxf(q1 * inv - mean1 * mean1, 0.f);
    float std0 = sqrtf(var0 + 1e-30f);
    float std1 = sqrtf(var1 + 1e-30f);
    if (end == beg) { mx0 = mx1 = 0.f; mn0 = mn1 = 0.f; }
    uint32_t* xh = g_Xh + (size_t)v * 224;
    uint32_t* xl = g_Xl + (size_t)v * 224;
    uint32_t uh, ul;
    split_pack(mean0, mean1, uh, ul); xh[lane] = uh;        xl[lane] = ul;
    split_pack(mx0, mx1, uh, ul);     xh[32 + lane] = uh;   xl[32 + lane] = ul;
    split_pack(mn0, mn1, uh, ul);     xh[64 + lane] = uh;   xl[64 + lane] = ul;
    split_pack(std0, std1, uh, ul);   xh[96 + lane] = uh;   xl[96 + lane] = ul;
    split_pack(var0, var1, uh, ul);   xh[128 + lane] = uh;  xl[128 + lane] = ul;
    split_pack(s0, s1, uh, ul);       xh[160 + lane] = uh;  xl[160 + lane] = ul;
    xh[192 + lane] = g_hH[(size_t)v * 32 + lane];
    xl[192 + lane] = g_hL[(size_t)v * 32 + lane];
    if (lane == 0) {
        float logD = logf(deg + 1.f);
        g_scal[2 * v]     = logD * (1.f / DELTA_F);
        g_scal[2 * v + 1] = (logD > 0.f) ? (DELTA_F / logD) : 0.f;
    }
}

// ======================= Z MMA + fused combine -> packed hu + BN1 stats ==================
#define ZS_AH 0
#define ZS_AL 18432
#define ZS_BH 36864
#define ZS_BL 62464
#define Z_STAGE 88064
#define ZS_BU (2 * Z_STAGE)
#define Z_SMEM (2 * Z_STAGE + 256)

__global__ __launch_bounds__(256) void zmma_kernel(const float* __restrict__ bU, int layer)
{
    extern __shared__ char dsm[];
    uint32_t sb = smem_u32(dsm);
    int tid = threadIdx.x, w = tid >> 5, l = tid & 31, g = l >> 2, t = l & 3;
    int tB = blockIdx.x * 128;
    if (tid < 64) ((float*)(dsm + ZS_BU))[tid] = bU[tid];

    const uint32_t* BzH = g_BzKh + (size_t)layer * 43008;
    const uint32_t* BzL = g_BzKl + (size_t)layer * 43008;

    float c[96];
#pragma unroll
    for (int i = 0; i < 96; i++) c[i] = 0.f;

    uint32_t aAoff = (uint32_t)(w * 16 + (l & 15)) * 144 + (uint32_t)(l >> 4) * 16;
    uint32_t aBoff = (uint32_t)(l & 15) * 400 + (uint32_t)(l >> 4) * 16;

    // prefetch chunk 0
    {
        uint32_t bs = sb;
        for (int i = tid; i < 1024; i += 256) {
            int r = i >> 3, j = i & 7;
            uint32_t d = (uint32_t)(r * 144 + j * 16);
            CP16(bs + ZS_AH + d, g_Xh + (size_t)(tB + r) * 224 + j * 4);
            CP16(bs + ZS_AL + d, g_Xl + (size_t)(tB + r) * 224 + j * 4);
        }
        for (int i = tid; i < 1536; i += 256) {
            int kr = i / 24, j = i - kr * 24;
            uint32_t d = (uint32_t)(kr * 400 + j * 16);
            CP16(bs + ZS_BH + d, BzH + kr * 96 + j * 4);
            CP16(bs + ZS_BL + d, BzL + kr * 96 + j * 4);
        }
        CP_COMMIT();
    }

    for (int ch = 0; ch < 7; ch++) {
        if (ch < 6) {
            uint32_t bs = sb + ((ch + 1) & 1) * Z_STAGE;
            int kc = (ch + 1) * 32;
            const uint32_t* Bh = BzH + (size_t)(ch + 1) * 6144;
            const uint32_t* Bl = BzL + (size_t)(ch + 1) * 6144;
            for (int i = tid; i < 1024; i += 256) {
                int r = i >> 3, j = i & 7;
                uint32_t d = (uint32_t)(r * 144 + j * 16);
                CP16(bs + ZS_AH + d, g_Xh + (size_t)(tB + r) * 224 + kc + j * 4);
                CP16(bs + ZS_AL + d, g_Xl + (size_t)(tB + r) * 224 + kc + j * 4);
            }
            for (int i = tid; i < 1536; i += 256) {
                int kr = i / 24, j = i - kr * 24;
                uint32_t d = (uint32_t)(kr * 400 + j * 16);
                CP16(bs + ZS_BH + d, Bh + kr * 96 + j * 4);
                CP16(bs + ZS_BL + d, Bl + kr * 96 + j * 4);
            }
            CP_COMMIT();
            CP_WAIT(1);
        } else {
            CP_WAIT(0);
        }
        __syncthreads();

        uint32_t bufOff = (ch & 1) * Z_STAGE;
        uint32_t aAh = sb + bufOff + ZS_AH + aAoff, aAl = sb + bufOff + ZS_AL + aAoff;
        uint32_t aBh = sb + bufOff + ZS_BH + aBoff, aBl = sb + bufOff + ZS_BL + aBoff;
#pragma unroll
        for (int ks = 0; ks < 4; ks++) {
            uint32_t ah[4], al[4];
            ldsm4(ah, aAh + ks * 32);
            ldsm4(al, aAl + ks * 32);
#pragma unroll
            for (int nn = 0; nn < 12; nn++) {
                uint32_t bh[4], bl[4];
                ldsm4t(bh, aBh + ks * 16 * 400 + nn * 32);
                ldsm4t(bl, aBl + ks * 16 * 400 + nn * 32);
                mma16816(c + nn * 8,     ah, bh[0], bh[1]);
                mma16816(c + nn * 8 + 4, ah, bh[2], bh[3]);
                mma16816(c + nn * 8,     ah, bl[0], bl[1]);
                mma16816(c + nn * 8 + 4, ah, bl[2], bl[3]);
                mma16816(c + nn * 8,     al, bh[0], bh[1]);
                mma16816(c + nn * 8 + 4, al, bh[2], bh[3]);
            }
        }
        __syncthreads();
    }

    // fused combine epilogue
    int r0 = w * 16 + g, r1 = r0 + 8;
    int gr0 = tB + r0, gr1 = tB + r1;
    float amp0 = g_scal[2 * gr0], att0 = g_scal[2 * gr0 + 1];
    float amp1 = g_scal[2 * gr1], att1 = g_scal[2 * gr1 + 1];
    const float* buS = (const float*)(dsm + ZS_BU);
    float* stage = (float*)dsm;
#pragma unroll
    for (int jj = 0; jj < 8; jj++) {
        int col = jj * 8 + 2 * t;
        float b0v = buS[col], b1v = buS[col + 1];
        stage[r0 * 66 + col]     = (c[jj*4+0] + amp0 * c[(jj+8)*4+0] + att0 * c[(jj+16)*4+0] + b0v) * SNORM;
        stage[r0 * 66 + col + 1] = (c[jj*4+1] + amp0 * c[(jj+8)*4+1] + att0 * c[(jj+16)*4+1] + b1v) * SNORM;
        stage[r1 * 66 + col]     = (c[jj*4+2] + amp1 * c[(jj+8)*4+2] + att1 * c[(jj+16)*4+2] + b0v) * SNORM;
        stage[r1 * 66 + col + 1] = (c[jj*4+3] + amp1 * c[(jj+8)*4+3] + att1 * c[(jj+16)*4+3] + b1v) * SNORM;
    }
    __syncthreads();
    // packed hu store
    for (int i = tid; i < 2048; i += 256) {
        int row = i >> 4, c4 = (i & 15) * 4;
        float4 v = make_float4(stage[row * 66 + c4],     stage[row * 66 + c4 + 1],
                               stage[row * 66 + c4 + 2], stage[row * 66 + c4 + 3]);
        uint32_t uh0, ul0, uh1, ul1;
        split_pack(v.x, v.y, uh0, ul0);
        split_pack(v.z, v.w, uh1, ul1);
        int pi = (tB + row) * 32 + (c4 >> 1);
        *(uint2*)(g_huH + pi) = make_uint2(uh0, uh1);
        *(uint2*)(g_huL + pi) = make_uint2(ul0, ul1);
    }
    // BN1 stats
    {
        int ci = tid & 63, hh = tid >> 6;
        float s = 0.f, q = 0.f;
        for (int r = hh * 32; r < hh * 32 + 32; r++) {
            if (tB + r < NN) { float x = stage[r * 66 + ci]; s += x; q += x * x; }
        }
        atomicAdd(&g_stats[layer * 256 + ci], s);
        atomicAdd(&g_stats[layer * 256 + 64 + ci], q);
    }
}

// ======================= mix MMA: BN1-folded hu @ Wmix + leaky + residual + BN2 stats ====
#define MX_AH 0
#define MX_AL 18432
#define MX_BH 36864
#define MX_BL 46080
#define MX_CONST 55296          // sc1[64], sh1[64], bias[64], pbias[256]
#define MX_SMEM 57088

__global__ __launch_bounds__(256) void mix_kernel(
    const float* __restrict__ h_in, const float* __restrict__ Wmix,
    const float* __restrict__ bmix, const float* __restrict__ gt,
    const float* __restrict__ bt, int layer)
{
    extern __shared__ char dsm[];
    uint32_t sb = smem_u32(dsm);
    int tid = threadIdx.x, w = tid >> 5, l = tid & 31, g = l >> 2, t = l & 3;
    int tB = blockIdx.x * 128;

    // A = packed hu via cp.async
    for (int i = tid; i < 1024; i += 256) {
        int r = i >> 3, j = i & 7;
        uint32_t d = (uint32_t)(r * 144 + j * 16);
        CP16(sb + MX_AH + d, g_huH + (size_t)(tB + r) * 32 + j * 4);
        CP16(sb + MX_AL + d, g_huL + (size_t)(tB + r) * 32 + j * 4);
    }
    CP_COMMIT();

    float* cst = (float*)(dsm + MX_CONST);
    if (tid < 64) {
        float mu  = g_stats[layer * 256 + tid] * (1.f / NN);
        float var = g_stats[layer * 256 + 64 + tid] * (1.f / NN) - mu * mu;
        float iv  = rsqrtf(fmaxf(var, 0.f) + EPS_BN);
        float s   = gt[tid] * iv;
        cst[tid] = s;
        cst[64 + tid] = bt[tid] - mu * s;
    }
    __syncthreads();

    // folded weights W' = diag(sc1) @ Wmix, bf16 hi/lo K-major pairs
    for (int i = tid; i < 2048; i += 256) {
        int k = i >> 5, n2 = i & 31;
        float s = cst[k];
        float2 wv = *(const float2*)(Wmix + k * 64 + n2 * 2);
        uint32_t uh, ul; split_pack(s * wv.x, s * wv.y, uh, ul);
        uint32_t d = (uint32_t)(k * 144 + n2 * 4);
        *(uint32_t*)(dsm + MX_BH + d) = uh;
        *(uint32_t*)(dsm + MX_BL + d) = ul;
    }
    // partial bias: b'[n] = sum_k sh1[k]*Wmix[k][n]
    {
        int n = tid & 63, kq = tid >> 6;
        float pb = 0.f;
        for (int k = kq * 16; k < kq * 16 + 16; k++)
            pb += cst[64 + k] * Wmix[k * 64 + n];
        cst[192 + tid] = pb;
    }
    CP_WAIT(0);
    __syncthreads();
    if (tid < 64)
        cst[128 + tid] = bmix[tid] + cst[192 + tid] + cst[256 + tid] + cst[320 + tid] + cst[384 + tid];

    float c[32];
#pragma unroll
    for (int i = 0; i < 32; i++) c[i] = 0.f;

    uint32_t aAoff = (uint32_t)(w * 16 + (l & 15)) * 144 + (uint32_t)(l >> 4) * 16;
    uint32_t aBoff = (uint32_t)(l & 15) * 144 + (uint32_t)(l >> 4) * 16;
    uint32_t aAh = sb + MX_AH + aAoff, aAl = sb + MX_AL + aAoff;
    uint32_t aBh = sb + MX_BH + aBoff, aBl = sb + MX_BL + aBoff;
#pragma unroll
    for (int ks = 0; ks < 4; ks++) {
        uint32_t ah[4], al[4];
        ldsm4(ah, aAh + ks * 32);
        ldsm4(al, aAl + ks * 32);
#pragma unroll
        for (int nn = 0; nn < 4; nn++) {
            uint32_t bh[4], bl[4];
            ldsm4t(bh, aBh + ks * 16 * 144 + nn * 32);
            ldsm4t(bl, aBl + ks * 16 * 144 + nn * 32);
            mma16816(c + nn * 8,     ah, bh[0], bh[1]);
            mma16816(c + nn * 8 + 4, ah, bh[2], bh[3]);
            mma16816(c + nn * 8,     ah, bl[0], bl[1]);
            mma16816(c + nn * 8 + 4, ah, bl[2], bl[3]);
            mma16816(c + nn * 8,     al, bh[0], bh[1]);
            mma16816(c + nn * 8 + 4, al, bh[2], bh[3]);
        }
    }
    __syncthreads();

    // epilogue: +bias, leaky, +h_in -> stage
    float* stage = (float*)dsm;
    int r0 = w * 16 + g, r1 = r0 + 8;
    int gr0 = tB + r0, gr1 = tB + r1;
#pragma unroll
    for (int jj = 0; jj < 8; jj++) {
        int col = jj * 8 + 2 * t;
        float bb0 = cst[128 + col], bb1 = cst[128 + col + 1];
        float a0 = c[jj * 4 + 0] + bb0, a1 = c[jj * 4 + 1] + bb1;
        float a2 = c[jj * 4 + 2] + bb0, a3 = c[jj * 4 + 3] + bb1;
        a0 = (a0 > 0.f) ? a0 : 0.01f * a0;
        a1 = (a1 > 0.f) ? a1 : 0.01f * a1;
        a2 = (a2 > 0.f) ? a2 : 0.01f * a2;
        a3 = (a3 > 0.f) ? a3 : 0.01f * a3;
        float h0 = 0.f, h1 = 0.f, h2 = 0.f, h3 = 0.f;
        if (gr0 < NN) { float2 hv = *(const float2*)(h_in + (size_t)gr0 * 64 + col); h0 = hv.x; h1 = hv.y; }
        if (gr1 < NN) { float2 hv = *(const float2*)(h_in + (size_t)gr1 * 64 + col); h2 = hv.x; h3 = hv.y; }
        stage[r0 * 66 + col]     = a0 + h0;
        stage[r0 * 66 + col + 1] = a1 + h1;
        stage[r1 * 66 + col]     = a2 + h2;
        stage[r1 * 66 + col + 1] = a3 + h3;
    }
    __syncthreads();
    for (int i = tid; i < 2048; i += 256) {
        int row = i >> 4, c4 = (i & 15) * 4;
        int gr = tB + row;
        if (gr < NN) {
            float4 v = make_float4(stage[row * 66 + c4],     stage[row * 66 + c4 + 1],
                                   stage[row * 66 + c4 + 2], stage[row * 66 + c4 + 3]);
            *(float4*)(g_ot + (size_t)gr * 64 + c4) = v;
        }
    }
    {
        int ci = tid & 63, hh = tid >> 6;
        float s = 0.f, q = 0.f;
        for (int r = hh * 32; r < hh * 32 + 32; r++) {
            if (tB + r < NN) { float x = stage[r * 66 + ci]; s += x; q += x * x; }
        }
        atomicAdd(&g_stats[layer * 256 + 128 + ci], s);
        atomicAdd(&g_stats[layer * 256 + 192 + ci], q);
    }
}

// ======================= final (layer 3 only): BN2 + relu + residual -> d_out ============
__global__ void final_kernel(const float* __restrict__ h_in,
                             const float* __restrict__ go,
                             const float* __restrict__ bo,
                             float* __restrict__ h_out, int layer)
{
    int i = blockIdx.x * blockDim.x + threadIdx.x;
    if (i >= NN * 32) return;
    int p = i & 31;
    int c0 = 2 * p;
    float mu0  = g_stats[layer * 256 + 128 + c0] * (1.f / NN);
    float mu1  = g_stats[layer * 256 + 128 + c0 + 1] * (1.f / NN);
    float var0 = g_stats[layer * 256 + 192 + c0] * (1.f / NN) - mu0 * mu0;
    float var1 = g_stats[layer * 256 + 192 + c0 + 1] * (1.f / NN) - mu1 * mu1;
    float iv0  = rsqrtf(fmaxf(var0, 0.f) + EPS_BN);
    float iv1  = rsqrtf(fmaxf(var1, 0.f) + EPS_BN);
    float2 ot = *(const float2*)(g_ot + (size_t)i * 2);
    float2 hi = *(const float2*)(h_in + (size_t)i * 2);
    float v0 = fmaxf((ot.x - mu0) * iv0 * go[c0]     + bo[c0],     0.f) + hi.x;
    float v1 = fmaxf((ot.y - mu1) * iv1 * go[c0 + 1] + bo[c0 + 1], 0.f) + hi.y;
    *(float2*)(h_out + (size_t)i * 2) = make_float2(v0, v1);
}

// ======================= host =======================
extern "C" void kernel_launch(void* const* d_in, const int* in_sizes, int n_in,
                              void* d_out, int out_size)
{
    (void)in_sizes; (void)n_in; (void)out_size;
    const float* node_feat = (const float*)d_in[0];
    const int*   esrc = (const int*)d_in[2];
    const int*   edst = (const int*)d_in[3];
    const float* WM   = (const float*)d_in[4];
    const float* bM   = (const float*)d_in[5];
    const float* WU   = (const float*)d_in[6];
    const float* bU   = (const float*)d_in[7];
    const float* gt   = (const float*)d_in[8];
    const float* bt   = (const float*)d_in[9];
    const float* Wmix = (const float*)d_in[10];
    const float* bmix = (const float*)d_in[11];
    const float* go   = (const float*)d_in[12];
    const float* bo   = (const float*)d_in[13];
    float* out = (float*)d_out;

    cudaFuncSetAttribute(zmma_kernel, cudaFuncAttributeMaxDynamicSharedMemorySize, Z_SMEM);
    cudaFuncSetAttribute(pqmma_kernel, cudaFuncAttributeMaxDynamicSharedMemorySize, P_SMEM);
    cudaFuncSetAttribute(mix_kernel, cudaFuncAttributeMaxDynamicSharedMemorySize, MX_SMEM);

    float *phA, *phB, *pot;
    cudaGetSymbolAddress((void**)&phA, g_hA);
    cudaGetSymbolAddress((void**)&phB, g_hB);
    cudaGetSymbolAddress((void**)&pot, g_ot);

    // setup: weights prepack (all layers) + stats/deg zero, CSR build
    prepack_all_kernel<<<936, 256>>>(WM, WU);
    hist_kernel<<<(NE + 255) / 256, 256>>>(edst);
    scan_kernel<<<1, 1024>>>();
    scatter_kernel<<<(NE + 255) / 256, 256>>>(esrc, edst);

    // h chain: h0=node_feat, h1=phA, h2=phB, h3=phA
    const float* hptr[4] = { node_feat, phA, phB, phA };

    for (int lyr = 0; lyr < 4; lyr++) {
        if (lyr == 0)
            pqmma_kernel<<<NTILES, 256, P_SMEM>>>(node_feat, node_feat, go, bo,
                                                  phA, 0, 0, 0);
        else
            pqmma_kernel<<<NTILES, 256, P_SMEM>>>(pot, hptr[lyr - 1],
                                                  go + (lyr - 1) * 64, bo + (lyr - 1) * 64,
                                                  (float*)hptr[lyr], lyr - 1, lyr, 1);
        agg_kernel<<<(NN + 7) / 8, 256>>>(bM + lyr * 64);
        zmma_kernel<<<NTILES, 256, Z_SMEM>>>(bU + lyr * 64, lyr);
        mix_kernel<<<NTILES, 256, MX_SMEM>>>(hptr[lyr], Wmix + (size_t)lyr * 4096,
                                             bmix + lyr * 64, gt + lyr * 64,
                                             bt + lyr * 64, lyr);
    }
    final_kernel<<<(NN * 32 + 255) / 256, 256>>>(hptr[3], go + 3 * 64, bo + 3 * 64, out, 3);
}